// round 1
// baseline (speedup 1.0000x reference)
#include <cuda_runtime.h>
#include <math.h>

// Problem constants
#define BATCH   4
#define T_SEQ   4096
#define DMODEL  512
#define HDIM    128
#define M_ROWS  (BATCH * T_SEQ)   // 16384

// ---------------- scratch (device globals: allocation-free) ----------------
__device__ float g_q[BATCH * T_SEQ * HDIM];
__device__ float g_k[BATCH * T_SEQ * HDIM];
__device__ float g_v[BATCH * T_SEQ * HDIM];

// ============================================================================
// QKV projection GEMM: out[M=16384, N=128] = x[M,512] @ W[512,128] + bias
// BM=64, BN=128 (full N), BK=32, 256 threads, 4x8 register tile per thread.
// blockIdx.y in {0,1,2} selects (wq,bq)->g_q, (wk,bk)->g_k, (wv,bv)->g_v.
// ============================================================================
__global__ __launch_bounds__(256) void qkv_gemm_kernel(
    const float* __restrict__ x,
    const float* __restrict__ wq, const float* __restrict__ bq,
    const float* __restrict__ wk, const float* __restrict__ bk,
    const float* __restrict__ wv, const float* __restrict__ bv)
{
    const float* W;
    const float* bias;
    float* out;
    if (blockIdx.y == 0)      { W = wq; bias = bq; out = g_q; }
    else if (blockIdx.y == 1) { W = wk; bias = bk; out = g_k; }
    else                      { W = wv; bias = bv; out = g_v; }

    __shared__ float As[64][33];    // padded: bank = (r + k) % 32
    __shared__ float Bs[32][128];

    const int tid = threadIdx.x;
    const int ty  = tid >> 4;       // 0..15
    const int tx  = tid & 15;       // 0..15
    const int m0  = blockIdx.x * 64;

    float acc[4][8];
#pragma unroll
    for (int i = 0; i < 4; i++)
#pragma unroll
        for (int j = 0; j < 8; j++) acc[i][j] = 0.f;

    for (int k0 = 0; k0 < DMODEL; k0 += 32) {
        // load A tile 64x32 (2 float4 per thread), scalar smem stores (padded)
#pragma unroll
        for (int it = 0; it < 2; it++) {
            int idx = tid + it * 256;          // float4 index 0..511
            int r   = idx >> 3;                // 64 rows, 8 float4/row
            int c4  = idx & 7;
            float4 v = *(const float4*)(x + (size_t)(m0 + r) * DMODEL + k0 + c4 * 4);
            As[r][c4 * 4 + 0] = v.x;
            As[r][c4 * 4 + 1] = v.y;
            As[r][c4 * 4 + 2] = v.z;
            As[r][c4 * 4 + 3] = v.w;
        }
        // load B tile 32x128 (4 float4 per thread)
#pragma unroll
        for (int it = 0; it < 4; it++) {
            int idx = tid + it * 256;          // float4 index 0..1023
            int r   = idx >> 5;
            int c4  = idx & 31;
            *(float4*)&Bs[r][c4 * 4] = *(const float4*)(W + (size_t)(k0 + r) * HDIM + c4 * 4);
        }
        __syncthreads();

#pragma unroll 8
        for (int k = 0; k < 32; k++) {
            float a[4], b[8];
#pragma unroll
            for (int i = 0; i < 4; i++) a[i] = As[ty * 4 + i][k];
#pragma unroll
            for (int u = 0; u < 2; u++) {
                float4 t = *(float4*)&Bs[k][tx * 4 + u * 64];
                b[u * 4 + 0] = t.x; b[u * 4 + 1] = t.y;
                b[u * 4 + 2] = t.z; b[u * 4 + 3] = t.w;
            }
#pragma unroll
            for (int i = 0; i < 4; i++)
#pragma unroll
                for (int j = 0; j < 8; j++)
                    acc[i][j] += a[i] * b[j];
        }
        __syncthreads();
    }

    // epilogue: add bias, store
#pragma unroll
    for (int i = 0; i < 4; i++) {
        int row = m0 + ty * 4 + i;
#pragma unroll
        for (int u = 0; u < 2; u++) {
            int col = tx * 4 + u * 64;
            float4 bo = *(const float4*)(bias + col);
            float4 o;
            o.x = acc[i][u * 4 + 0] + bo.x;
            o.y = acc[i][u * 4 + 1] + bo.y;
            o.z = acc[i][u * 4 + 2] + bo.z;
            o.w = acc[i][u * 4 + 3] + bo.w;
            *(float4*)(out + (size_t)row * HDIM + col) = o;
        }
    }
}

// ============================================================================
// Flash attention (causal), fp32.
// BM=64 q-rows, BN=64 k-rows per tile, head dim 128, 128 threads.
// S thread grid: 16(ty) x 8(tx), s[4 rows][8 cols] per thread.
// O thread grid: same, acc[4 rows][4 u][4] -> cols tx*4 + u*32.
// Online softmax with 8-lane shfl reductions.
// ============================================================================
#define BM  64
#define BN  64
#define LDQ 129     // padded row stride (floats): bank = (r + k) % 32
#define LDK 129
#define LDV 132     // 16B-aligned stride for float4 smem ops
#define LDP 65

__global__ __launch_bounds__(128) void attn_kernel(float* __restrict__ out)
{
    extern __shared__ float sm[];
    float* Qs = sm;                    // BM * LDQ
    float* Ks = Qs + BM * LDQ;         // BN * LDK
    float* Vs = Ks + BN * LDK;         // BN * LDV
    float* Ps = Vs + BN * LDV;         // BM * LDP

    const int b  = blockIdx.y;
    const int qt = (int)(gridDim.x - 1) - (int)blockIdx.x;   // heavy tiles first
    const int q0 = qt * BM;

    const float* qptr = g_q + (size_t)b * T_SEQ * HDIM;
    const float* kptr = g_k + (size_t)b * T_SEQ * HDIM;
    const float* vptr = g_v + (size_t)b * T_SEQ * HDIM;

    const int tid = threadIdx.x;
    const int ty  = tid >> 3;   // 0..15
    const int tx  = tid & 7;    // 0..7

    const float scale = 0.08838834764831845f;   // 1/sqrt(128)

    // load Q tile (64 x 128), pre-scaled
#pragma unroll
    for (int it = 0; it < 16; it++) {
        int idx = tid + it * 128;     // float4 index 0..2047
        int r   = idx >> 5;
        int c4  = idx & 31;
        float4 v = *(const float4*)(qptr + (size_t)(q0 + r) * HDIM + c4 * 4);
        Qs[r * LDQ + c4 * 4 + 0] = v.x * scale;
        Qs[r * LDQ + c4 * 4 + 1] = v.y * scale;
        Qs[r * LDQ + c4 * 4 + 2] = v.z * scale;
        Qs[r * LDQ + c4 * 4 + 3] = v.w * scale;
    }

    float acc[4][4][4];
#pragma unroll
    for (int i = 0; i < 4; i++)
#pragma unroll
        for (int u = 0; u < 4; u++)
#pragma unroll
            for (int w = 0; w < 4; w++) acc[i][u][w] = 0.f;

    float mrow[4], lrow[4];
#pragma unroll
    for (int i = 0; i < 4; i++) { mrow[i] = -1e30f; lrow[i] = 0.f; }

    for (int kt = 0; kt <= qt; kt++) {
        const int k0 = kt * BN;

        // load K and V tiles (each 64 x 128)
#pragma unroll
        for (int it = 0; it < 16; it++) {
            int idx = tid + it * 128;
            int r   = idx >> 5;
            int c4  = idx & 31;
            float4 kv = *(const float4*)(kptr + (size_t)(k0 + r) * HDIM + c4 * 4);
            Ks[r * LDK + c4 * 4 + 0] = kv.x;
            Ks[r * LDK + c4 * 4 + 1] = kv.y;
            Ks[r * LDK + c4 * 4 + 2] = kv.z;
            Ks[r * LDK + c4 * 4 + 3] = kv.w;
            float4 vv = *(const float4*)(vptr + (size_t)(k0 + r) * HDIM + c4 * 4);
            *(float4*)&Vs[r * LDV + c4 * 4] = vv;
        }
        __syncthreads();   // tiles ready (also covers Q-tile on first iter)

        // ---- S = Q K^T (tile) ----
        float s[4][8];
#pragma unroll
        for (int i = 0; i < 4; i++)
#pragma unroll
            for (int j = 0; j < 8; j++) s[i][j] = 0.f;

#pragma unroll 4
        for (int k = 0; k < HDIM; k++) {
            float a[4], bk_[8];
#pragma unroll
            for (int i = 0; i < 4; i++) a[i] = Qs[(ty * 4 + i) * LDQ + k];
#pragma unroll
            for (int j = 0; j < 8; j++) bk_[j] = Ks[(tx * 8 + j) * LDK + k];
#pragma unroll
            for (int i = 0; i < 4; i++)
#pragma unroll
                for (int j = 0; j < 8; j++)
                    s[i][j] += a[i] * bk_[j];
        }

        // ---- online softmax ----
        const bool diag = (kt == qt);
#pragma unroll
        for (int i = 0; i < 4; i++) {
            const int qrow = q0 + ty * 4 + i;
            if (diag) {
#pragma unroll
                for (int j = 0; j < 8; j++)
                    if (k0 + tx * 8 + j > qrow) s[i][j] = -1e30f;
            }
            float mv = s[i][0];
#pragma unroll
            for (int j = 1; j < 8; j++) mv = fmaxf(mv, s[i][j]);
            mv = fmaxf(mv, __shfl_xor_sync(0xffffffffu, mv, 1));
            mv = fmaxf(mv, __shfl_xor_sync(0xffffffffu, mv, 2));
            mv = fmaxf(mv, __shfl_xor_sync(0xffffffffu, mv, 4));
            const float mn = fmaxf(mrow[i], mv);

            float rs = 0.f;
#pragma unroll
            for (int j = 0; j < 8; j++) {
                float p = __expf(s[i][j] - mn);
                s[i][j] = p;
                rs += p;
            }
            rs += __shfl_xor_sync(0xffffffffu, rs, 1);
            rs += __shfl_xor_sync(0xffffffffu, rs, 2);
            rs += __shfl_xor_sync(0xffffffffu, rs, 4);

            const float alpha = __expf(mrow[i] - mn);
            mrow[i] = mn;
            lrow[i] = lrow[i] * alpha + rs;
#pragma unroll
            for (int u = 0; u < 4; u++)
#pragma unroll
                for (int w = 0; w < 4; w++) acc[i][u][w] *= alpha;
#pragma unroll
            for (int j = 0; j < 8; j++)
                Ps[(ty * 4 + i) * LDP + tx * 8 + j] = s[i][j];
        }
        __syncthreads();   // P visible to all

        // ---- O += P V ----
#pragma unroll 2
        for (int j = 0; j < BN; j++) {
            float p[4];
#pragma unroll
            for (int i = 0; i < 4; i++) p[i] = Ps[(ty * 4 + i) * LDP + j];
#pragma unroll
            for (int u = 0; u < 4; u++) {
                float4 v = *(float4*)&Vs[j * LDV + tx * 4 + u * 32];
#pragma unroll
                for (int i = 0; i < 4; i++) {
                    acc[i][u][0] += p[i] * v.x;
                    acc[i][u][1] += p[i] * v.y;
                    acc[i][u][2] += p[i] * v.z;
                    acc[i][u][3] += p[i] * v.w;
                }
            }
        }
        __syncthreads();   // done reading Ps/Vs before next tile overwrites
    }

    // ---- epilogue: O / l ----
#pragma unroll
    for (int i = 0; i < 4; i++) {
        const int qrow = q0 + ty * 4 + i;
        const float inv = 1.f / lrow[i];
        float* orow = out + ((size_t)b * T_SEQ + qrow) * HDIM;
#pragma unroll
        for (int u = 0; u < 4; u++) {
            const int col = tx * 4 + u * 32;
            float4 o;
            o.x = acc[i][u][0] * inv;
            o.y = acc[i][u][1] * inv;
            o.z = acc[i][u][2] * inv;
            o.w = acc[i][u][3] * inv;
            *(float4*)(orow + col) = o;
        }
    }
}

// ============================================================================
// launch
// ============================================================================
extern "C" void kernel_launch(void* const* d_in, const int* in_sizes, int n_in,
                              void* d_out, int out_size)
{
    (void)in_sizes; (void)n_in; (void)out_size;
    const float* x  = (const float*)d_in[0];
    // d_in[1] = mask (int32 causal tril) -- causality applied analytically
    const float* wq = (const float*)d_in[2];
    const float* bq = (const float*)d_in[3];
    const float* wk = (const float*)d_in[4];
    const float* bk = (const float*)d_in[5];
    const float* wv = (const float*)d_in[6];
    const float* bv = (const float*)d_in[7];
    float* out = (float*)d_out;

    dim3 g1(M_ROWS / 64, 3);
    qkv_gemm_kernel<<<g1, 256>>>(x, wq, bq, wk, bk, wv, bv);

    const int smem_bytes = (BM * LDQ + BN * LDK + BN * LDV + BM * LDP) * (int)sizeof(float);
    cudaFuncSetAttribute(attn_kernel, cudaFuncAttributeMaxDynamicSharedMemorySize, smem_bytes);
    dim3 g2(T_SEQ / BM, BATCH);
    attn_kernel<<<g2, 128, smem_bytes>>>(out);
}

// round 4
// speedup vs baseline: 1.3318x; 1.3318x over previous
#include <cuda_runtime.h>
#include <math.h>

// Problem constants
#define BATCH   4
#define T_SEQ   4096
#define DMODEL  512
#define HDIM    128
#define M_ROWS  (BATCH * T_SEQ)   // 16384

// ---------------- scratch (device globals: allocation-free) ----------------
__device__ float g_q[BATCH * T_SEQ * HDIM];
__device__ float g_k[BATCH * T_SEQ * HDIM];
__device__ float g_v[BATCH * T_SEQ * HDIM];

// ============================================================================
// QKV projection GEMM: out[M=16384, N=128] = x[M,512] @ W[512,128] + bias
// BM=128, BN=128, BK=32, 256 threads, 8x8 register tile per thread.
// A stored transposed in smem (As[k][m]) so both operand loads are LDS.128.
// blockIdx.y in {0,1,2} selects (wq,bq)->g_q, (wk,bk)->g_k, (wv,bv)->g_v.
// ============================================================================
#define GLDA 132
#define GLDB 132

__global__ __launch_bounds__(256) void qkv_gemm_kernel(
    const float* __restrict__ x,
    const float* __restrict__ wq, const float* __restrict__ bq,
    const float* __restrict__ wk, const float* __restrict__ bk,
    const float* __restrict__ wv, const float* __restrict__ bv)
{
    const float* W;
    const float* bias;
    float* out;
    if (blockIdx.y == 0)      { W = wq; bias = bq; out = g_q; }
    else if (blockIdx.y == 1) { W = wk; bias = bk; out = g_k; }
    else                      { W = wv; bias = bv; out = g_v; }

    __shared__ float As[32][GLDA];   // As[k][m]  (transposed)
    __shared__ float Bs[32][GLDB];   // Bs[k][n]

    const int tid = threadIdx.x;
    const int ty  = tid >> 4;        // 0..15
    const int tx  = tid & 15;        // 0..15
    const int m0  = blockIdx.x * 128;

    float acc[2][4][2][4];           // [iu][i][ju][j]
#pragma unroll
    for (int a = 0; a < 2; a++)
#pragma unroll
        for (int i = 0; i < 4; i++)
#pragma unroll
            for (int c = 0; c < 2; c++)
#pragma unroll
                for (int j = 0; j < 4; j++) acc[a][i][c][j] = 0.f;

    for (int k0 = 0; k0 < DMODEL; k0 += 32) {
        // A tile: 128 rows x 32 cols, stored transposed (4 float4 per thread)
#pragma unroll
        for (int it = 0; it < 4; it++) {
            int idx = tid + it * 256;            // 0..1023
            int r   = idx >> 3;                  // 0..127
            int c4  = idx & 7;                   // 0..7
            float4 v = *(const float4*)(x + (size_t)(m0 + r) * DMODEL + k0 + c4 * 4);
            As[c4 * 4 + 0][r] = v.x;
            As[c4 * 4 + 1][r] = v.y;
            As[c4 * 4 + 2][r] = v.z;
            As[c4 * 4 + 3][r] = v.w;
        }
        // B tile: 32 rows x 128 cols (4 float4 per thread)
#pragma unroll
        for (int it = 0; it < 4; it++) {
            int idx = tid + it * 256;            // 0..1023
            int r   = idx >> 5;                  // 0..31
            int c4  = idx & 31;
            *(float4*)&Bs[r][c4 * 4] = *(const float4*)(W + (size_t)(k0 + r) * HDIM + c4 * 4);
        }
        __syncthreads();

#pragma unroll 8
        for (int k = 0; k < 32; k++) {
            float4 a0 = *(float4*)&As[k][ty * 4];
            float4 a1 = *(float4*)&As[k][ty * 4 + 64];
            float4 b0 = *(float4*)&Bs[k][tx * 4];
            float4 b1 = *(float4*)&Bs[k][tx * 4 + 64];
            float av[2][4] = {{a0.x, a0.y, a0.z, a0.w}, {a1.x, a1.y, a1.z, a1.w}};
            float bv_[2][4] = {{b0.x, b0.y, b0.z, b0.w}, {b1.x, b1.y, b1.z, b1.w}};
#pragma unroll
            for (int a = 0; a < 2; a++)
#pragma unroll
                for (int i = 0; i < 4; i++)
#pragma unroll
                    for (int c = 0; c < 2; c++)
#pragma unroll
                        for (int j = 0; j < 4; j++)
                            acc[a][i][c][j] += av[a][i] * bv_[c][j];
        }
        __syncthreads();
    }

    // epilogue: bias + store
#pragma unroll
    for (int a = 0; a < 2; a++)
#pragma unroll
        for (int i = 0; i < 4; i++) {
            int row = m0 + a * 64 + ty * 4 + i;
#pragma unroll
            for (int c = 0; c < 2; c++) {
                int col = c * 64 + tx * 4;
                float4 bo = *(const float4*)(bias + col);
                float4 o;
                o.x = acc[a][i][c][0] + bo.x;
                o.y = acc[a][i][c][1] + bo.y;
                o.z = acc[a][i][c][2] + bo.z;
                o.w = acc[a][i][c][3] + bo.w;
                *(float4*)(out + (size_t)row * HDIM + col) = o;
            }
        }
}

// ============================================================================
// Flash attention (causal), fp32.
// BM=64 q-rows, BN=128 k-rows per tile, 256 threads (8 warps = 2/SMSP).
// S thread grid: 16(ty) x 16(tx); per-thread 4 rows x 8 strided cols
//   (col = tx + 16*j)  -> conflict-free scalar K loads.
// P staged TRANSPOSED (Pt[col][row], stride 68) -> PV p-load is one LDS.128.
// O tile per thread: 4 rows x 8 cols (cols tx*4 + u*64).
// ============================================================================
#define BM  64
#define BN  128
#define LDQ 129     // (scol + k) mod 32 conflict-free scalar reads
#define LDK 129
#define LDV 132     // float4-aligned
#define LDPT 68     // Pt[128][68], float4-aligned

__global__ __launch_bounds__(256) void attn_kernel(float* __restrict__ out)
{
    extern __shared__ float sm[];
    float* Qs = sm;                     // BM * LDQ      =  8256
    float* Ks = Qs + BM * LDQ;          // BN * LDK      = 16512
    float* Vs = Ks + BN * LDK;          // BN * LDV      = 16896
    float* Pt = Vs + BN * LDV;          // BN * LDPT     =  8704
    // total 50368 floats = 201472 bytes

    const int b  = blockIdx.y;
    const int qt = (int)(gridDim.x - 1) - (int)blockIdx.x;   // heavy tiles first
    const int q0 = qt * BM;

    const float* qptr = g_q + (size_t)b * T_SEQ * HDIM;
    const float* kptr = g_k + (size_t)b * T_SEQ * HDIM;
    const float* vptr = g_v + (size_t)b * T_SEQ * HDIM;

    const int tid = threadIdx.x;
    const int ty  = tid >> 4;   // 0..15
    const int tx  = tid & 15;   // 0..15

    const float scale = 0.08838834764831845f;   // 1/sqrt(128)

    // load Q tile (64 x 128), pre-scaled: 8 float4 per thread
#pragma unroll
    for (int it = 0; it < 8; it++) {
        int idx = tid + it * 256;     // 0..2047
        int r   = idx >> 5;           // 0..63
        int c4  = idx & 31;
        float4 v = *(const float4*)(qptr + (size_t)(q0 + r) * HDIM + c4 * 4);
        Qs[r * LDQ + c4 * 4 + 0] = v.x * scale;
        Qs[r * LDQ + c4 * 4 + 1] = v.y * scale;
        Qs[r * LDQ + c4 * 4 + 2] = v.z * scale;
        Qs[r * LDQ + c4 * 4 + 3] = v.w * scale;
    }

    float acc[4][2][4];
#pragma unroll
    for (int i = 0; i < 4; i++)
#pragma unroll
        for (int u = 0; u < 2; u++)
#pragma unroll
            for (int w = 0; w < 4; w++) acc[i][u][w] = 0.f;

    float mrow[4], lrow[4];
#pragma unroll
    for (int i = 0; i < 4; i++) { mrow[i] = -1e30f; lrow[i] = 0.f; }

    const int kt_last = qt >> 1;
    for (int kt = 0; kt <= kt_last; kt++) {
        const int k0 = kt * BN;

        // load K and V tiles (each 128 x 128): 16 float4 per thread each
#pragma unroll
        for (int it = 0; it < 16; it++) {
            int idx = tid + it * 256;     // 0..4095
            int r   = idx >> 5;           // 0..127
            int c4  = idx & 31;
            float4 kv = *(const float4*)(kptr + (size_t)(k0 + r) * HDIM + c4 * 4);
            Ks[r * LDK + c4 * 4 + 0] = kv.x;
            Ks[r * LDK + c4 * 4 + 1] = kv.y;
            Ks[r * LDK + c4 * 4 + 2] = kv.z;
            Ks[r * LDK + c4 * 4 + 3] = kv.w;
            float4 vv = *(const float4*)(vptr + (size_t)(k0 + r) * HDIM + c4 * 4);
            *(float4*)&Vs[r * LDV + c4 * 4] = vv;
        }
        __syncthreads();   // tiles ready (covers Q tile on first iter too)

        // ---- S = Q K^T : per-thread 4 rows x 8 strided cols ----
        float s[4][8];
#pragma unroll
        for (int i = 0; i < 4; i++)
#pragma unroll
            for (int j = 0; j < 8; j++) s[i][j] = 0.f;

#pragma unroll 2
        for (int k = 0; k < HDIM; k++) {
            float a[4], bk_[8];
#pragma unroll
            for (int i = 0; i < 4; i++) a[i] = Qs[(ty * 4 + i) * LDQ + k];
#pragma unroll
            for (int j = 0; j < 8; j++) bk_[j] = Ks[(tx + 16 * j) * LDK + k];
#pragma unroll
            for (int i = 0; i < 4; i++)
#pragma unroll
                for (int j = 0; j < 8; j++)
                    s[i][j] += a[i] * bk_[j];
        }

        // ---- online softmax (row reduce across 16 tx lanes) ----
        const bool diag = (kt == kt_last);
#pragma unroll
        for (int i = 0; i < 4; i++) {
            const int qrow = q0 + ty * 4 + i;
            if (diag) {
#pragma unroll
                for (int j = 0; j < 8; j++)
                    if (k0 + tx + 16 * j > qrow) s[i][j] = -1e30f;
            }
            float mv = s[i][0];
#pragma unroll
            for (int j = 1; j < 8; j++) mv = fmaxf(mv, s[i][j]);
            mv = fmaxf(mv, __shfl_xor_sync(0xffffffffu, mv, 1));
            mv = fmaxf(mv, __shfl_xor_sync(0xffffffffu, mv, 2));
            mv = fmaxf(mv, __shfl_xor_sync(0xffffffffu, mv, 4));
            mv = fmaxf(mv, __shfl_xor_sync(0xffffffffu, mv, 8));
            const float mn = fmaxf(mrow[i], mv);

            float rs = 0.f;
#pragma unroll
            for (int j = 0; j < 8; j++) {
                float p = __expf(s[i][j] - mn);
                s[i][j] = p;
                rs += p;
            }
            rs += __shfl_xor_sync(0xffffffffu, rs, 1);
            rs += __shfl_xor_sync(0xffffffffu, rs, 2);
            rs += __shfl_xor_sync(0xffffffffu, rs, 4);
            rs += __shfl_xor_sync(0xffffffffu, rs, 8);

            const float alpha = __expf(mrow[i] - mn);
            mrow[i] = mn;
            lrow[i] = lrow[i] * alpha + rs;
#pragma unroll
            for (int u = 0; u < 2; u++)
#pragma unroll
                for (int w = 0; w < 4; w++) acc[i][u][w] *= alpha;
            // store P transposed: Pt[col][row]
#pragma unroll
            for (int j = 0; j < 8; j++)
                Pt[(tx + 16 * j) * LDPT + ty * 4 + i] = s[i][j];
        }
        __syncthreads();   // Pt visible to all

        // ---- O += P V : per j2, 1 LDS.128 (p) + 2 LDS.128 (v) + 32 FMA ----
#pragma unroll 2
        for (int j2 = 0; j2 < BN; j2++) {
            float4 pv = *(float4*)&Pt[j2 * LDPT + ty * 4];
            float p[4] = {pv.x, pv.y, pv.z, pv.w};
            float4 v0 = *(float4*)&Vs[j2 * LDV + tx * 4];
            float4 v1 = *(float4*)&Vs[j2 * LDV + tx * 4 + 64];
#pragma unroll
            for (int i = 0; i < 4; i++) {
                acc[i][0][0] += p[i] * v0.x;
                acc[i][0][1] += p[i] * v0.y;
                acc[i][0][2] += p[i] * v0.z;
                acc[i][0][3] += p[i] * v0.w;
                acc[i][1][0] += p[i] * v1.x;
                acc[i][1][1] += p[i] * v1.y;
                acc[i][1][2] += p[i] * v1.z;
                acc[i][1][3] += p[i] * v1.w;
            }
        }
        __syncthreads();   // done reading Pt/Vs before next tile overwrites
    }

    // ---- epilogue: O / l ----
#pragma unroll
    for (int i = 0; i < 4; i++) {
        const int qrow = q0 + ty * 4 + i;
        const float inv = 1.f / lrow[i];
        float* orow = out + ((size_t)b * T_SEQ + qrow) * HDIM;
#pragma unroll
        for (int u = 0; u < 2; u++) {
            const int col = tx * 4 + u * 64;
            float4 o;
            o.x = acc[i][u][0] * inv;
            o.y = acc[i][u][1] * inv;
            o.z = acc[i][u][2] * inv;
            o.w = acc[i][u][3] * inv;
            *(float4*)(orow + col) = o;
        }
    }
}

// ============================================================================
// launch
// ============================================================================
extern "C" void kernel_launch(void* const* d_in, const int* in_sizes, int n_in,
                              void* d_out, int out_size)
{
    (void)in_sizes; (void)n_in; (void)out_size;
    const float* x  = (const float*)d_in[0];
    // d_in[1] = mask (int32 causal tril) -- causality applied analytically
    const float* wq = (const float*)d_in[2];
    const float* bq = (const float*)d_in[3];
    const float* wk = (const float*)d_in[4];
    const float* bk = (const float*)d_in[5];
    const float* wv = (const float*)d_in[6];
    const float* bv = (const float*)d_in[7];
    float* out = (float*)d_out;

    dim3 g1(M_ROWS / 128, 3);
    qkv_gemm_kernel<<<g1, 256>>>(x, wq, bq, wk, bk, wv, bv);

    const int smem_bytes = (BM * LDQ + BN * LDK + BN * LDV + BN * LDPT) * (int)sizeof(float);
    cudaFuncSetAttribute(attn_kernel, cudaFuncAttributeMaxDynamicSharedMemorySize, smem_bytes);
    dim3 g2(T_SEQ / BM, BATCH);
    attn_kernel<<<g2, 256, smem_bytes>>>(out);
}

// round 6
// speedup vs baseline: 1.7968x; 1.3492x over previous
#include <cuda_runtime.h>
#include <math.h>

// Problem constants
#define BATCH   4
#define T_SEQ   4096
#define DMODEL  512
#define HDIM    128
#define M_ROWS  (BATCH * T_SEQ)   // 16384

typedef unsigned long long ull;

// ---------------- f32x2 packed helpers (Blackwell FFMA2 path) ----------------
__device__ __forceinline__ ull ffma2(ull a, ull b, ull c) {
    ull d;
    asm("fma.rn.f32x2 %0, %1, %2, %3;" : "=l"(d) : "l"(a), "l"(b), "l"(c));
    return d;
}
__device__ __forceinline__ ull fmul2(ull a, ull b) {
    ull d;
    asm("mul.rn.f32x2 %0, %1, %2;" : "=l"(d) : "l"(a), "l"(b));
    return d;
}
__device__ __forceinline__ ull fdup(float x) {
    ull d; unsigned u = __float_as_uint(x);
    asm("mov.b64 %0, {%1, %1};" : "=l"(d) : "r"(u));
    return d;
}
__device__ __forceinline__ float f2lo(ull v) { return __uint_as_float((unsigned)v); }
__device__ __forceinline__ float f2hi(ull v) { return __uint_as_float((unsigned)(v >> 32)); }

// ---------------- scratch (device globals: allocation-free) ----------------
__device__ float g_q[BATCH * T_SEQ * HDIM];
__device__ float g_k[BATCH * T_SEQ * HDIM];
__device__ float g_v[BATCH * T_SEQ * HDIM];

// ============================================================================
// QKV projection GEMM: out[M=16384, N=128] = x[M,512] @ W[512,128] + bias
// BM=128, BN=128, BK=32, 256 threads, 8x8 register tile, FFMA2 over col-pairs.
// ============================================================================
#define GLDA 132
#define GLDB 132

__global__ __launch_bounds__(256) void qkv_gemm_kernel(
    const float* __restrict__ x,
    const float* __restrict__ wq, const float* __restrict__ bq,
    const float* __restrict__ wk, const float* __restrict__ bk,
    const float* __restrict__ wv, const float* __restrict__ bv)
{
    const float* W;
    const float* bias;
    float* out;
    if (blockIdx.y == 0)      { W = wq; bias = bq; out = g_q; }
    else if (blockIdx.y == 1) { W = wk; bias = bk; out = g_k; }
    else                      { W = wv; bias = bv; out = g_v; }

    __shared__ float As[32][GLDA];   // As[k][m]  (transposed)
    __shared__ float Bs[32][GLDB];   // Bs[k][n]

    const int tid = threadIdx.x;
    const int ty  = tid >> 4;        // 0..15
    const int tx  = tid & 15;        // 0..15
    const int m0  = blockIdx.x * 128;

    // acc2[a-half][row i][c-half][col-pair]  : cols (c*64 + tx*4 + 2*p, +1)
    ull acc2[2][4][2][2];
#pragma unroll
    for (int a = 0; a < 2; a++)
#pragma unroll
        for (int i = 0; i < 4; i++)
#pragma unroll
            for (int c = 0; c < 2; c++)
#pragma unroll
                for (int p = 0; p < 2; p++) acc2[a][i][c][p] = 0ull;

    for (int k0 = 0; k0 < DMODEL; k0 += 32) {
        // A tile: 128 rows x 32 cols, stored transposed
#pragma unroll
        for (int it = 0; it < 4; it++) {
            int idx = tid + it * 256;
            int r   = idx >> 3;
            int c4  = idx & 7;
            float4 v = *(const float4*)(x + (size_t)(m0 + r) * DMODEL + k0 + c4 * 4);
            As[c4 * 4 + 0][r] = v.x;
            As[c4 * 4 + 1][r] = v.y;
            As[c4 * 4 + 2][r] = v.z;
            As[c4 * 4 + 3][r] = v.w;
        }
        // B tile: 32 rows x 128 cols
#pragma unroll
        for (int it = 0; it < 4; it++) {
            int idx = tid + it * 256;
            int r   = idx >> 5;
            int c4  = idx & 31;
            *(float4*)&Bs[r][c4 * 4] = *(const float4*)(W + (size_t)(k0 + r) * HDIM + c4 * 4);
        }
        __syncthreads();

#pragma unroll 8
        for (int k = 0; k < 32; k++) {
            float4 a0 = *(float4*)&As[k][ty * 4];
            float4 a1 = *(float4*)&As[k][ty * 4 + 64];
            ulonglong2 b0 = *(ulonglong2*)&Bs[k][tx * 4];
            ulonglong2 b1 = *(ulonglong2*)&Bs[k][tx * 4 + 64];
            ull a2[2][4];
            a2[0][0] = fdup(a0.x); a2[0][1] = fdup(a0.y);
            a2[0][2] = fdup(a0.z); a2[0][3] = fdup(a0.w);
            a2[1][0] = fdup(a1.x); a2[1][1] = fdup(a1.y);
            a2[1][2] = fdup(a1.z); a2[1][3] = fdup(a1.w);
#pragma unroll
            for (int a = 0; a < 2; a++)
#pragma unroll
                for (int i = 0; i < 4; i++) {
                    acc2[a][i][0][0] = ffma2(a2[a][i], b0.x, acc2[a][i][0][0]);
                    acc2[a][i][0][1] = ffma2(a2[a][i], b0.y, acc2[a][i][0][1]);
                    acc2[a][i][1][0] = ffma2(a2[a][i], b1.x, acc2[a][i][1][0]);
                    acc2[a][i][1][1] = ffma2(a2[a][i], b1.y, acc2[a][i][1][1]);
                }
        }
        __syncthreads();
    }

    // epilogue: bias + store
#pragma unroll
    for (int a = 0; a < 2; a++)
#pragma unroll
        for (int i = 0; i < 4; i++) {
            int row = m0 + a * 64 + ty * 4 + i;
#pragma unroll
            for (int c = 0; c < 2; c++) {
                int col = c * 64 + tx * 4;
                float4 bo = *(const float4*)(bias + col);
                float4 o;
                o.x = f2lo(acc2[a][i][c][0]) + bo.x;
                o.y = f2hi(acc2[a][i][c][0]) + bo.y;
                o.z = f2lo(acc2[a][i][c][1]) + bo.z;
                o.w = f2hi(acc2[a][i][c][1]) + bo.w;
                *(float4*)(out + (size_t)row * HDIM + col) = o;
            }
        }
}

// ============================================================================
// Flash attention (causal), fp32 with FFMA2 packed math.
// BM=64 q-rows, BN=128 k-rows/tile, 256 threads (8 warps).
// S: per-thread 4 rows x 8 strided cols (col = tx + 16j), k paired into f32x2
//    (lo/hi = even/odd-k partial sums, summed at softmax). All LDS are .128.
// PV: acc f32x2 over column pairs; V float4 gives natural pairs; P dup'd.
// All smem row-major, strides multiple of 4 floats.
// ============================================================================
#define BM  64
#define BN  128
#define LDQ 132
#define LDK 132
#define LDV 132
#define LDP 132

__global__ __launch_bounds__(256) void attn_kernel(float* __restrict__ out)
{
    extern __shared__ float sm[];
    float* Qs = sm;                     // BM * LDQ =  8448
    float* Ks = Qs + BM * LDQ;          // BN * LDK = 16896
    float* Vs = Ks + BN * LDK;          // BN * LDV = 16896
    float* Ps = Vs + BN * LDV;          // BM * LDP =  8448
    // total 50688 floats = 202752 bytes

    const int b  = blockIdx.y;
    const int qt = (int)(gridDim.x - 1) - (int)blockIdx.x;   // heavy tiles first
    const int q0 = qt * BM;

    const float* qptr = g_q + (size_t)b * T_SEQ * HDIM;
    const float* kptr = g_k + (size_t)b * T_SEQ * HDIM;
    const float* vptr = g_v + (size_t)b * T_SEQ * HDIM;

    const int tid = threadIdx.x;
    const int ty  = tid >> 4;   // 0..15
    const int tx  = tid & 15;   // 0..15

    const float scale = 0.08838834764831845f;   // 1/sqrt(128)

    // load Q tile (64 x 128), pre-scaled, contiguous STS.128
#pragma unroll
    for (int it = 0; it < 8; it++) {
        int idx = tid + it * 256;
        int r   = idx >> 5;
        int c4  = idx & 31;
        float4 v = *(const float4*)(qptr + (size_t)(q0 + r) * HDIM + c4 * 4);
        v.x *= scale; v.y *= scale; v.z *= scale; v.w *= scale;
        *(float4*)&Qs[r * LDQ + c4 * 4] = v;
    }

    // acc2[row i][col-pair]: cols { tx*4+0..3, tx*4+64..67 } as 4 pairs
    ull acc2[4][4];
#pragma unroll
    for (int i = 0; i < 4; i++)
#pragma unroll
        for (int p = 0; p < 4; p++) acc2[i][p] = 0ull;

    float mrow[4], lrow[4];
#pragma unroll
    for (int i = 0; i < 4; i++) { mrow[i] = -1e30f; lrow[i] = 0.f; }

    const int kt_last = qt >> 1;
    for (int kt = 0; kt <= kt_last; kt++) {
        const int kb = kt * BN;

        // load K and V tiles (128 x 128 each), contiguous STS.128
#pragma unroll
        for (int it = 0; it < 16; it++) {
            int idx = tid + it * 256;
            int r   = idx >> 5;
            int c4  = idx & 31;
            float4 kv = *(const float4*)(kptr + (size_t)(kb + r) * HDIM + c4 * 4);
            *(float4*)&Ks[r * LDK + c4 * 4] = kv;
            float4 vv = *(const float4*)(vptr + (size_t)(kb + r) * HDIM + c4 * 4);
            *(float4*)&Vs[r * LDV + c4 * 4] = vv;
        }
        __syncthreads();

        // ---- S = Q K^T : k paired into f32x2 ----
        ull s2[4][8];
#pragma unroll
        for (int i = 0; i < 4; i++)
#pragma unroll
            for (int j = 0; j < 8; j++) s2[i][j] = 0ull;

#pragma unroll 8
        for (int k0 = 0; k0 < HDIM; k0 += 4) {
            ulonglong2 a[4];
#pragma unroll
            for (int i = 0; i < 4; i++)
                a[i] = *(const ulonglong2*)&Qs[(ty * 4 + i) * LDQ + k0];
#pragma unroll
            for (int j = 0; j < 8; j++) {
                ulonglong2 bk = *(const ulonglong2*)&Ks[(tx + 16 * j) * LDK + k0];
#pragma unroll
                for (int i = 0; i < 4; i++) {
                    s2[i][j] = ffma2(a[i].x, bk.x, s2[i][j]);
                    s2[i][j] = ffma2(a[i].y, bk.y, s2[i][j]);
                }
            }
        }

        // ---- online softmax ----
        const bool diag = (kt == kt_last);
#pragma unroll
        for (int i = 0; i < 4; i++) {
            const int qrow = q0 + ty * 4 + i;
            float s[8];
#pragma unroll
            for (int j = 0; j < 8; j++) s[j] = f2lo(s2[i][j]) + f2hi(s2[i][j]);
            if (diag) {
#pragma unroll
                for (int j = 0; j < 8; j++)
                    if (kb + tx + 16 * j > qrow) s[j] = -1e30f;
            }
            float mv = s[0];
#pragma unroll
            for (int j = 1; j < 8; j++) mv = fmaxf(mv, s[j]);
            mv = fmaxf(mv, __shfl_xor_sync(0xffffffffu, mv, 1));
            mv = fmaxf(mv, __shfl_xor_sync(0xffffffffu, mv, 2));
            mv = fmaxf(mv, __shfl_xor_sync(0xffffffffu, mv, 4));
            mv = fmaxf(mv, __shfl_xor_sync(0xffffffffu, mv, 8));
            const float mn = fmaxf(mrow[i], mv);

            float rs = 0.f;
#pragma unroll
            for (int j = 0; j < 8; j++) {
                float p = __expf(s[j] - mn);
                s[j] = p;
                rs += p;
            }
            rs += __shfl_xor_sync(0xffffffffu, rs, 1);
            rs += __shfl_xor_sync(0xffffffffu, rs, 2);
            rs += __shfl_xor_sync(0xffffffffu, rs, 4);
            rs += __shfl_xor_sync(0xffffffffu, rs, 8);

            const float alpha = __expf(mrow[i] - mn);
            mrow[i] = mn;
            lrow[i] = lrow[i] * alpha + rs;
            ull al2 = fdup(alpha);
#pragma unroll
            for (int p = 0; p < 4; p++) acc2[i][p] = fmul2(acc2[i][p], al2);
            // store P row-major (bank = tx + 16*ty + const : conflict-free)
#pragma unroll
            for (int j = 0; j < 8; j++)
                Ps[(ty * 4 + i) * LDP + tx + 16 * j] = s[j];
        }
        __syncthreads();   // P visible to all

        // ---- O += P V : col-paired f32x2, P dup'd ----
#pragma unroll 2
        for (int j0 = 0; j0 < BN; j0 += 4) {
            float4 pr[4];
#pragma unroll
            for (int i = 0; i < 4; i++)
                pr[i] = *(float4*)&Ps[(ty * 4 + i) * LDP + j0];
            ull p2[4][4];
#pragma unroll
            for (int i = 0; i < 4; i++) {
                p2[i][0] = fdup(pr[i].x);
                p2[i][1] = fdup(pr[i].y);
                p2[i][2] = fdup(pr[i].z);
                p2[i][3] = fdup(pr[i].w);
            }
#pragma unroll
            for (int jj = 0; jj < 4; jj++) {
                ulonglong2 v0 = *(ulonglong2*)&Vs[(j0 + jj) * LDV + tx * 4];
                ulonglong2 v1 = *(ulonglong2*)&Vs[(j0 + jj) * LDV + tx * 4 + 64];
#pragma unroll
                for (int i = 0; i < 4; i++) {
                    acc2[i][0] = ffma2(p2[i][jj], v0.x, acc2[i][0]);
                    acc2[i][1] = ffma2(p2[i][jj], v0.y, acc2[i][1]);
                    acc2[i][2] = ffma2(p2[i][jj], v1.x, acc2[i][2]);
                    acc2[i][3] = ffma2(p2[i][jj], v1.y, acc2[i][3]);
                }
            }
        }
        __syncthreads();   // done reading Ps/Vs before next tile overwrites
    }

    // ---- epilogue: O / l ----
#pragma unroll
    for (int i = 0; i < 4; i++) {
        const int qrow = q0 + ty * 4 + i;
        const float inv = 1.f / lrow[i];
        float* orow = out + ((size_t)b * T_SEQ + qrow) * HDIM;
        float4 o0, o1;
        o0.x = f2lo(acc2[i][0]) * inv;
        o0.y = f2hi(acc2[i][0]) * inv;
        o0.z = f2lo(acc2[i][1]) * inv;
        o0.w = f2hi(acc2[i][1]) * inv;
        o1.x = f2lo(acc2[i][2]) * inv;
        o1.y = f2hi(acc2[i][2]) * inv;
        o1.z = f2lo(acc2[i][3]) * inv;
        o1.w = f2hi(acc2[i][3]) * inv;
        *(float4*)(orow + tx * 4)      = o0;
        *(float4*)(orow + tx * 4 + 64) = o1;
    }
}

// ============================================================================
// launch
// ============================================================================
extern "C" void kernel_launch(void* const* d_in, const int* in_sizes, int n_in,
                              void* d_out, int out_size)
{
    (void)in_sizes; (void)n_in; (void)out_size;
    const float* x  = (const float*)d_in[0];
    // d_in[1] = mask (int32 causal tril) -- causality applied analytically
    const float* wq = (const float*)d_in[2];
    const float* bq = (const float*)d_in[3];
    const float* wk = (const float*)d_in[4];
    const float* bk = (const float*)d_in[5];
    const float* wv = (const float*)d_in[6];
    const float* bv = (const float*)d_in[7];
    float* out = (float*)d_out;

    dim3 g1(M_ROWS / 128, 3);
    qkv_gemm_kernel<<<g1, 256>>>(x, wq, bq, wk, bk, wv, bv);

    const int smem_bytes = (BM * LDQ + BN * LDK + BN * LDV + BM * LDP) * (int)sizeof(float);
    cudaFuncSetAttribute(attn_kernel, cudaFuncAttributeMaxDynamicSharedMemorySize, smem_bytes);
    dim3 g2(T_SEQ / BM, BATCH);
    attn_kernel<<<g2, 256, smem_bytes>>>(out);
}

// round 8
// speedup vs baseline: 3.3727x; 1.8771x over previous
#include <cuda_runtime.h>
#include <cuda_bf16.h>
#include <math.h>
#include <stdint.h>

// Problem constants
#define BATCH   4
#define T_SEQ   4096
#define DMODEL  512
#define HDIM    128
#define M_ROWS  (BATCH * T_SEQ)   // 16384

typedef unsigned long long ull;

// ---------------- f32x2 packed helpers (GEMM FFMA2 path) ----------------
__device__ __forceinline__ ull ffma2(ull a, ull b, ull c) {
    ull d;
    asm("fma.rn.f32x2 %0, %1, %2, %3;" : "=l"(d) : "l"(a), "l"(b), "l"(c));
    return d;
}
__device__ __forceinline__ ull fdup(float x) {
    ull d; unsigned u = __float_as_uint(x);
    asm("mov.b64 %0, {%1, %1};" : "=l"(d) : "r"(u));
    return d;
}
__device__ __forceinline__ float f2lo(ull v) { return __uint_as_float((unsigned)v); }
__device__ __forceinline__ float f2hi(ull v) { return __uint_as_float((unsigned)(v >> 32)); }

// pack two floats to bf16x2 word: lo 16 bits = first arg
__device__ __forceinline__ uint32_t packbf2(float lo, float hi) {
    uint32_t r;
    asm("cvt.rn.satfinite.bf16x2.f32 %0, %1, %2;" : "=r"(r) : "f"(hi), "f"(lo));
    return r;
}
__device__ __forceinline__ float bflo(uint32_t w) { return __uint_as_float(w << 16); }
__device__ __forceinline__ float bfhi(uint32_t w) { return __uint_as_float(w & 0xffff0000u); }

// ---------------- scratch (device globals: allocation-free) ----------------
__device__ __nv_bfloat16 g_qhi[M_ROWS * HDIM];
__device__ __nv_bfloat16 g_qlo[M_ROWS * HDIM];
__device__ __nv_bfloat16 g_khi[M_ROWS * HDIM];
__device__ __nv_bfloat16 g_klo[M_ROWS * HDIM];
__device__ __nv_bfloat16 g_vhi[M_ROWS * HDIM];
__device__ __nv_bfloat16 g_vlo[M_ROWS * HDIM];

// ---------------- mma / ldmatrix helpers (base-target ISA) ----------------
__device__ __forceinline__ uint32_t smem_u32(const void* p) {
    uint32_t a;
    asm("{ .reg .u64 t; cvta.to.shared.u64 t, %1; cvt.u32.u64 %0, t; }" : "=r"(a) : "l"(p));
    return a;
}
__device__ __forceinline__ void mma_bf16(float* c, const uint32_t* a, uint32_t b0, uint32_t b1) {
    asm volatile(
        "mma.sync.aligned.m16n8k16.row.col.f32.bf16.bf16.f32 "
        "{%0,%1,%2,%3},{%4,%5,%6,%7},{%8,%9},{%0,%1,%2,%3};"
        : "+f"(c[0]), "+f"(c[1]), "+f"(c[2]), "+f"(c[3])
        : "r"(a[0]), "r"(a[1]), "r"(a[2]), "r"(a[3]), "r"(b0), "r"(b1));
}
__device__ __forceinline__ void ldmx4(uint32_t* r, uint32_t addr) {
    asm volatile("ldmatrix.sync.aligned.m8n8.x4.shared.b16 {%0,%1,%2,%3}, [%4];"
                 : "=r"(r[0]), "=r"(r[1]), "=r"(r[2]), "=r"(r[3]) : "r"(addr));
}
__device__ __forceinline__ void ldmx2(uint32_t& r0, uint32_t& r1, uint32_t addr) {
    asm volatile("ldmatrix.sync.aligned.m8n8.x2.shared.b16 {%0,%1}, [%2];"
                 : "=r"(r0), "=r"(r1) : "r"(addr));
}
__device__ __forceinline__ void ldmx2t(uint32_t& r0, uint32_t& r1, uint32_t addr) {
    asm volatile("ldmatrix.sync.aligned.m8n8.x2.trans.shared.b16 {%0,%1}, [%2];"
                 : "=r"(r0), "=r"(r1) : "r"(addr));
}

// ============================================================================
// QKV projection GEMM (FFMA2, BM=128/BN=128/BK=32, 256 thr).
// Epilogue splits result to bf16 hi/lo (Q pre-scaled by 1/sqrt(H)).
// ============================================================================
#define GLDA 132
#define GLDB 132

__global__ __launch_bounds__(256) void qkv_gemm_kernel(
    const float* __restrict__ x,
    const float* __restrict__ wq, const float* __restrict__ bq,
    const float* __restrict__ wk, const float* __restrict__ bk,
    const float* __restrict__ wv, const float* __restrict__ bv)
{
    const float* W;
    const float* bias;
    if (blockIdx.y == 0)      { W = wq; bias = bq; }
    else if (blockIdx.y == 1) { W = wk; bias = bk; }
    else                      { W = wv; bias = bv; }

    __shared__ float As[32][GLDA];   // transposed
    __shared__ float Bs[32][GLDB];

    const int tid = threadIdx.x;
    const int ty  = tid >> 4;
    const int tx  = tid & 15;
    const int m0  = blockIdx.x * 128;

    ull acc2[2][4][2][2];
#pragma unroll
    for (int a = 0; a < 2; a++)
#pragma unroll
        for (int i = 0; i < 4; i++)
#pragma unroll
            for (int c = 0; c < 2; c++)
#pragma unroll
                for (int p = 0; p < 2; p++) acc2[a][i][c][p] = 0ull;

    for (int k0 = 0; k0 < DMODEL; k0 += 32) {
#pragma unroll
        for (int it = 0; it < 4; it++) {
            int idx = tid + it * 256;
            int r   = idx >> 3;
            int c4  = idx & 7;
            float4 v = *(const float4*)(x + (size_t)(m0 + r) * DMODEL + k0 + c4 * 4);
            As[c4 * 4 + 0][r] = v.x;
            As[c4 * 4 + 1][r] = v.y;
            As[c4 * 4 + 2][r] = v.z;
            As[c4 * 4 + 3][r] = v.w;
        }
#pragma unroll
        for (int it = 0; it < 4; it++) {
            int idx = tid + it * 256;
            int r   = idx >> 5;
            int c4  = idx & 31;
            *(float4*)&Bs[r][c4 * 4] = *(const float4*)(W + (size_t)(k0 + r) * HDIM + c4 * 4);
        }
        __syncthreads();

#pragma unroll 8
        for (int k = 0; k < 32; k++) {
            float4 a0 = *(float4*)&As[k][ty * 4];
            float4 a1 = *(float4*)&As[k][ty * 4 + 64];
            ulonglong2 b0 = *(ulonglong2*)&Bs[k][tx * 4];
            ulonglong2 b1 = *(ulonglong2*)&Bs[k][tx * 4 + 64];
            ull a2[2][4];
            a2[0][0] = fdup(a0.x); a2[0][1] = fdup(a0.y);
            a2[0][2] = fdup(a0.z); a2[0][3] = fdup(a0.w);
            a2[1][0] = fdup(a1.x); a2[1][1] = fdup(a1.y);
            a2[1][2] = fdup(a1.z); a2[1][3] = fdup(a1.w);
#pragma unroll
            for (int a = 0; a < 2; a++)
#pragma unroll
                for (int i = 0; i < 4; i++) {
                    acc2[a][i][0][0] = ffma2(a2[a][i], b0.x, acc2[a][i][0][0]);
                    acc2[a][i][0][1] = ffma2(a2[a][i], b0.y, acc2[a][i][0][1]);
                    acc2[a][i][1][0] = ffma2(a2[a][i], b1.x, acc2[a][i][1][0]);
                    acc2[a][i][1][1] = ffma2(a2[a][i], b1.y, acc2[a][i][1][1]);
                }
        }
        __syncthreads();
    }

    const int y = blockIdx.y;
    const float sc = (y == 0) ? 0.08838834764831845f : 1.0f;   // 1/sqrt(128) into Q
    __nv_bfloat16* hiA = (y == 0) ? g_qhi : (y == 1) ? g_khi : g_vhi;
    __nv_bfloat16* loA = (y == 0) ? g_qlo : (y == 1) ? g_klo : g_vlo;

#pragma unroll
    for (int a = 0; a < 2; a++)
#pragma unroll
        for (int i = 0; i < 4; i++) {
            int row = m0 + a * 64 + ty * 4 + i;
#pragma unroll
            for (int c = 0; c < 2; c++) {
                int col = c * 64 + tx * 4;
                float4 bo = *(const float4*)(bias + col);
                float o0 = (f2lo(acc2[a][i][c][0]) + bo.x) * sc;
                float o1 = (f2hi(acc2[a][i][c][0]) + bo.y) * sc;
                float o2 = (f2lo(acc2[a][i][c][1]) + bo.z) * sc;
                float o3 = (f2hi(acc2[a][i][c][1]) + bo.w) * sc;
                uint32_t wh0 = packbf2(o0, o1);
                uint32_t wh1 = packbf2(o2, o3);
                float r0 = o0 - bflo(wh0);
                float r1 = o1 - bfhi(wh0);
                float r2 = o2 - bflo(wh1);
                float r3 = o3 - bfhi(wh1);
                *(uint2*)(&hiA[(size_t)row * HDIM + col]) = make_uint2(wh0, wh1);
                *(uint2*)(&loA[(size_t)row * HDIM + col]) =
                    make_uint2(packbf2(r0, r1), packbf2(r2, r3));
            }
        }
}

// ============================================================================
// FA2-style flash attention (causal), split-bf16 HMMA (mma.sync m16n8k16).
// BM=BN=64, 128 threads (4 warps); warp w owns q-rows 16w..16w+15.
// S: A=Q frags (regs), B=K via ldmatrix   (K smem [n][k] == col-major B)
// PV: A=P (register reuse of S C-frags),  B=V via ldmatrix.trans
// ============================================================================
#define LDT 136                         // smem row stride in bf16 (272B)
#define TILE_B (64 * LDT * 2)           // 17408 bytes per tile

__global__ __launch_bounds__(128) void attn_kernel(float* __restrict__ out)
{
    extern __shared__ char smem[];
    char* KHI = smem;
    char* KLO = KHI + TILE_B;
    char* VHI = KLO + TILE_B;
    char* VLO = VHI + TILE_B;
    const uint32_t uKHI = smem_u32(KHI);
    const uint32_t uKLO = uKHI + TILE_B;
    const uint32_t uVHI = uKLO + TILE_B;
    const uint32_t uVLO = uVHI + TILE_B;

    const int tid  = threadIdx.x;
    const int w    = tid >> 5;
    const int lane = tid & 31;
    const int b    = blockIdx.y;
    const int qt   = (int)(gridDim.x - 1) - (int)blockIdx.x;   // heavy tiles first
    const int q0   = qt * 64;

    const int grp  = lane >> 2;          // row within fragment group
    const int tic  = lane & 3;           // col pair selector
    const int qr0  = q0 + 16 * w + grp;  // this thread's two q-rows
    const int qr1  = qr0 + 8;

    // ---- stage Q tile (hi->KHI, lo->KLO), extract A fragments, release ----
    {
        const __nv_bfloat16* qh = g_qhi + ((size_t)b * T_SEQ + q0) * HDIM;
        const __nv_bfloat16* ql = g_qlo + ((size_t)b * T_SEQ + q0) * HDIM;
#pragma unroll
        for (int it = 0; it < 8; it++) {
            int idx = tid + it * 128;
            int r = idx >> 4, c = idx & 15;
            *(uint4*)(KHI + r * (LDT * 2) + c * 16) = *(const uint4*)(qh + (size_t)r * HDIM + c * 8);
            *(uint4*)(KLO + r * (LDT * 2) + c * 16) = *(const uint4*)(ql + (size_t)r * HDIM + c * 8);
        }
    }
    __syncthreads();

    uint32_t qhi[8][4], qlo[8][4];
    {
        const int rowQ = 16 * w + (lane & 15);
        const int colQ = (lane >> 4) * 8;
#pragma unroll
        for (int kc = 0; kc < 8; kc++) {
            uint32_t off = (uint32_t)(rowQ * LDT + kc * 16 + colQ) * 2;
            ldmx4(qhi[kc], uKHI + off);
            ldmx4(qlo[kc], uKLO + off);
        }
    }
    __syncthreads();

    float O[16][4];
#pragma unroll
    for (int j = 0; j < 16; j++)
#pragma unroll
        for (int c = 0; c < 4; c++) O[j][c] = 0.f;
    float m0 = -1e30f, m1 = -1e30f, l0 = 0.f, l1 = 0.f;

    // ldmatrix per-lane address components
    const int rowK = lane & 7;                 // K b-frag: row in n, col half in k
    const int colK = ((lane >> 3) & 1) * 8;
    const int rowV = lane & 15;                // V b-frag (trans): row in k

    const __nv_bfloat16* kh = g_khi + (size_t)b * T_SEQ * HDIM;
    const __nv_bfloat16* kl = g_klo + (size_t)b * T_SEQ * HDIM;
    const __nv_bfloat16* vh = g_vhi + (size_t)b * T_SEQ * HDIM;
    const __nv_bfloat16* vl = g_vlo + (size_t)b * T_SEQ * HDIM;

    for (int kt = 0; kt <= qt; kt++) {
        const int kb = kt * 64;

        // ---- load K/V hi/lo tiles (64 x 128 bf16 each) ----
#pragma unroll
        for (int it = 0; it < 8; it++) {
            int idx = tid + it * 128;
            int r = idx >> 4, c = idx & 15;
            size_t go = (size_t)(kb + r) * HDIM + c * 8;
            uint32_t so = r * (LDT * 2) + c * 16;
            *(uint4*)(KHI + so) = *(const uint4*)(kh + go);
            *(uint4*)(KLO + so) = *(const uint4*)(kl + go);
            *(uint4*)(VHI + so) = *(const uint4*)(vh + go);
            *(uint4*)(VLO + so) = *(const uint4*)(vl + go);
        }
        __syncthreads();

        // ---- S = Q K^T (split chain) ----
        float s[8][4];
#pragma unroll
        for (int j = 0; j < 8; j++)
#pragma unroll
            for (int c = 0; c < 4; c++) s[j][c] = 0.f;

#pragma unroll
        for (int j = 0; j < 8; j++) {
            const uint32_t offn = (uint32_t)((8 * j + rowK) * LDT + colK) * 2;
#pragma unroll
            for (int kc = 0; kc < 8; kc++) {
                uint32_t bh0, bh1, bl0, bl1;
                uint32_t off = offn + (uint32_t)(kc * 16) * 2;
                ldmx2(bh0, bh1, uKHI + off);
                ldmx2(bl0, bl1, uKLO + off);
                mma_bf16(s[j], qhi[kc], bh0, bh1);
                mma_bf16(s[j], qhi[kc], bl0, bl1);
                mma_bf16(s[j], qlo[kc], bh0, bh1);
            }
        }

        // ---- causal mask (diag tile only) ----
        if (kt == qt) {
            const int cb = kb + 2 * tic;
#pragma unroll
            for (int j = 0; j < 8; j++) {
                int c0 = cb + 8 * j, c1 = c0 + 1;
                if (c0 > qr0) s[j][0] = -1e30f;
                if (c1 > qr0) s[j][1] = -1e30f;
                if (c0 > qr1) s[j][2] = -1e30f;
                if (c1 > qr1) s[j][3] = -1e30f;
            }
        }

        // ---- online softmax (rows live in 4-lane groups) ----
        float mx0 = -1e30f, mx1 = -1e30f;
#pragma unroll
        for (int j = 0; j < 8; j++) {
            mx0 = fmaxf(mx0, fmaxf(s[j][0], s[j][1]));
            mx1 = fmaxf(mx1, fmaxf(s[j][2], s[j][3]));
        }
        mx0 = fmaxf(mx0, __shfl_xor_sync(0xffffffffu, mx0, 1));
        mx0 = fmaxf(mx0, __shfl_xor_sync(0xffffffffu, mx0, 2));
        mx1 = fmaxf(mx1, __shfl_xor_sync(0xffffffffu, mx1, 1));
        mx1 = fmaxf(mx1, __shfl_xor_sync(0xffffffffu, mx1, 2));
        const float mn0 = fmaxf(m0, mx0);
        const float mn1 = fmaxf(m1, mx1);
        const float al0 = __expf(m0 - mn0);
        const float al1 = __expf(m1 - mn1);
        m0 = mn0; m1 = mn1;

        uint32_t phi[8][2], plo[8][2];
        float la0 = 0.f, la1 = 0.f;
#pragma unroll
        for (int j = 0; j < 8; j++) {
            float p0 = __expf(s[j][0] - mn0);
            float p1 = __expf(s[j][1] - mn0);
            float p2 = __expf(s[j][2] - mn1);
            float p3 = __expf(s[j][3] - mn1);
            la0 += p0 + p1; la1 += p2 + p3;
            uint32_t h0 = packbf2(p0, p1);
            uint32_t h1 = packbf2(p2, p3);
            phi[j][0] = h0; phi[j][1] = h1;
            plo[j][0] = packbf2(p0 - bflo(h0), p1 - bfhi(h0));
            plo[j][1] = packbf2(p2 - bflo(h1), p3 - bfhi(h1));
        }
        la0 += __shfl_xor_sync(0xffffffffu, la0, 1);
        la0 += __shfl_xor_sync(0xffffffffu, la0, 2);
        la1 += __shfl_xor_sync(0xffffffffu, la1, 1);
        la1 += __shfl_xor_sync(0xffffffffu, la1, 2);
        l0 = l0 * al0 + la0;
        l1 = l1 * al1 + la1;

#pragma unroll
        for (int j = 0; j < 16; j++) {
            O[j][0] *= al0; O[j][1] *= al0;
            O[j][2] *= al1; O[j][3] *= al1;
        }

        // ---- O += P V (split chain), A frags from P registers ----
#pragma unroll
        for (int kc = 0; kc < 4; kc++) {
            uint32_t ah[4] = { phi[2 * kc][0], phi[2 * kc][1], phi[2 * kc + 1][0], phi[2 * kc + 1][1] };
            uint32_t al[4] = { plo[2 * kc][0], plo[2 * kc][1], plo[2 * kc + 1][0], plo[2 * kc + 1][1] };
            const uint32_t offk = (uint32_t)((16 * kc + rowV) * LDT) * 2;
#pragma unroll
            for (int jn = 0; jn < 16; jn++) {
                uint32_t vh0, vh1, vl0, vl1;
                uint32_t off = offk + (uint32_t)(8 * jn) * 2;
                ldmx2t(vh0, vh1, uVHI + off);
                ldmx2t(vl0, vl1, uVLO + off);
                mma_bf16(O[jn], ah, vh0, vh1);
                mma_bf16(O[jn], ah, vl0, vl1);
                mma_bf16(O[jn], al, vh0, vh1);
            }
        }
        __syncthreads();   // smem tiles reused next iteration
    }

    // ---- epilogue: O / l ----
    const float i0 = 1.f / l0;
    const float i1 = 1.f / l1;
    float* o0 = out + ((size_t)b * T_SEQ + qr0) * HDIM;
    float* o1 = out + ((size_t)b * T_SEQ + qr1) * HDIM;
#pragma unroll
    for (int jn = 0; jn < 16; jn++) {
        int col = 8 * jn + 2 * tic;
        float2 a = make_float2(O[jn][0] * i0, O[jn][1] * i0);
        float2 c = make_float2(O[jn][2] * i1, O[jn][3] * i1);
        *(float2*)(o0 + col) = a;
        *(float2*)(o1 + col) = c;
    }
}

// ============================================================================
// launch
// ============================================================================
extern "C" void kernel_launch(void* const* d_in, const int* in_sizes, int n_in,
                              void* d_out, int out_size)
{
    (void)in_sizes; (void)n_in; (void)out_size;
    const float* x  = (const float*)d_in[0];
    // d_in[1] = mask (int32 causal tril) -- causality applied analytically
    const float* wq = (const float*)d_in[2];
    const float* bq = (const float*)d_in[3];
    const float* wk = (const float*)d_in[4];
    const float* bk = (const float*)d_in[5];
    const float* wv = (const float*)d_in[6];
    const float* bv = (const float*)d_in[7];
    float* out = (float*)d_out;

    dim3 g1(M_ROWS / 128, 3);
    qkv_gemm_kernel<<<g1, 256>>>(x, wq, bq, wk, bk, wv, bv);

    const int smem_bytes = 4 * TILE_B;   // 69632
    cudaFuncSetAttribute(attn_kernel, cudaFuncAttributeMaxDynamicSharedMemorySize, smem_bytes);
    dim3 g2(T_SEQ / 64, BATCH);
    attn_kernel<<<g2, 128, smem_bytes>>>(out);
}

// round 9
// speedup vs baseline: 4.1464x; 1.2294x over previous
#include <cuda_runtime.h>
#include <cuda_bf16.h>
#include <math.h>
#include <stdint.h>

// Problem constants
#define BATCH   4
#define T_SEQ   4096
#define DMODEL  512
#define HDIM    128
#define M_ROWS  (BATCH * T_SEQ)   // 16384

// pack two floats to bf16x2 word: lo 16 bits = first arg
__device__ __forceinline__ uint32_t packbf2(float lo, float hi) {
    uint32_t r;
    asm("cvt.rn.satfinite.bf16x2.f32 %0, %1, %2;" : "=r"(r) : "f"(hi), "f"(lo));
    return r;
}
__device__ __forceinline__ float bflo(uint32_t w) { return __uint_as_float(w << 16); }
__device__ __forceinline__ float bfhi(uint32_t w) { return __uint_as_float(w & 0xffff0000u); }

// ---------------- scratch (device globals: allocation-free) ----------------
__device__ __nv_bfloat16 g_xhi[M_ROWS * DMODEL];
__device__ __nv_bfloat16 g_xlo[M_ROWS * DMODEL];
__device__ __nv_bfloat16 g_wthi[3 * HDIM * DMODEL];   // W^T [y][n][k]
__device__ __nv_bfloat16 g_wtlo[3 * HDIM * DMODEL];
__device__ __nv_bfloat16 g_qhi[M_ROWS * HDIM];
__device__ __nv_bfloat16 g_qlo[M_ROWS * HDIM];
__device__ __nv_bfloat16 g_khi[M_ROWS * HDIM];
__device__ __nv_bfloat16 g_klo[M_ROWS * HDIM];
__device__ __nv_bfloat16 g_vhi[M_ROWS * HDIM];
__device__ __nv_bfloat16 g_vlo[M_ROWS * HDIM];

// ---------------- mma / ldmatrix / cp.async helpers (base-target ISA) -------
__device__ __forceinline__ uint32_t smem_u32(const void* p) {
    uint32_t a;
    asm("{ .reg .u64 t; cvta.to.shared.u64 t, %1; cvt.u32.u64 %0, t; }" : "=r"(a) : "l"(p));
    return a;
}
__device__ __forceinline__ void mma_bf16(float* c, const uint32_t* a, uint32_t b0, uint32_t b1) {
    asm volatile(
        "mma.sync.aligned.m16n8k16.row.col.f32.bf16.bf16.f32 "
        "{%0,%1,%2,%3},{%4,%5,%6,%7},{%8,%9},{%0,%1,%2,%3};"
        : "+f"(c[0]), "+f"(c[1]), "+f"(c[2]), "+f"(c[3])
        : "r"(a[0]), "r"(a[1]), "r"(a[2]), "r"(a[3]), "r"(b0), "r"(b1));
}
__device__ __forceinline__ void ldmx4(uint32_t* r, uint32_t addr) {
    asm volatile("ldmatrix.sync.aligned.m8n8.x4.shared.b16 {%0,%1,%2,%3}, [%4];"
                 : "=r"(r[0]), "=r"(r[1]), "=r"(r[2]), "=r"(r[3]) : "r"(addr));
}
__device__ __forceinline__ void ldmx2(uint32_t& r0, uint32_t& r1, uint32_t addr) {
    asm volatile("ldmatrix.sync.aligned.m8n8.x2.shared.b16 {%0,%1}, [%2];"
                 : "=r"(r0), "=r"(r1) : "r"(addr));
}
__device__ __forceinline__ void ldmx2t(uint32_t& r0, uint32_t& r1, uint32_t addr) {
    asm volatile("ldmatrix.sync.aligned.m8n8.x2.trans.shared.b16 {%0,%1}, [%2];"
                 : "=r"(r0), "=r"(r1) : "r"(addr));
}
__device__ __forceinline__ void cp16(uint32_t dst, const void* src) {
    asm volatile("cp.async.cg.shared.global [%0], [%1], 16;" :: "r"(dst), "l"(src) : "memory");
}
__device__ __forceinline__ void cp_commit_wait() {
    asm volatile("cp.async.commit_group;" ::: "memory");
    asm volatile("cp.async.wait_group 0;" ::: "memory");
}

// ============================================================================
// Prep 1: split x (fp32) -> bf16 hi/lo
// ============================================================================
__global__ __launch_bounds__(256) void split_x_kernel(const float* __restrict__ x)
{
    const int idx = blockIdx.x * 256 + threadIdx.x;     // float4 index
    float4 v = ((const float4*)x)[idx];
    uint32_t h0 = packbf2(v.x, v.y);
    uint32_t h1 = packbf2(v.z, v.w);
    float r0 = v.x - bflo(h0), r1 = v.y - bfhi(h0);
    float r2 = v.z - bflo(h1), r3 = v.w - bfhi(h1);
    *(uint2*)&g_xhi[(size_t)idx * 4] = make_uint2(h0, h1);
    *(uint2*)&g_xlo[(size_t)idx * 4] = make_uint2(packbf2(r0, r1), packbf2(r2, r3));
}

// ============================================================================
// Prep 2: transpose + split W [K=512][N=128] -> Wt [N][K] bf16 hi/lo, 3 mats
// ============================================================================
__global__ __launch_bounds__(256) void w_split_kernel(
    const float* __restrict__ wq, const float* __restrict__ wk, const float* __restrict__ wv)
{
    __shared__ float ts[32][33];
    const float* W = (blockIdx.z == 0) ? wq : (blockIdx.z == 1) ? wk : wv;
    const int k0 = blockIdx.x * 32;
    const int n0 = blockIdx.y * 32;
    const int txx = threadIdx.x & 31;
    const int tyy = threadIdx.x >> 5;   // 0..7
#pragma unroll
    for (int r = 0; r < 4; r++)
        ts[tyy + r * 8][txx] = W[(size_t)(k0 + tyy + r * 8) * HDIM + n0 + txx];
    __syncthreads();
#pragma unroll
    for (int r = 0; r < 4; r++) {
        int n = n0 + tyy + r * 8;
        int k = k0 + txx;
        float v = ts[txx][tyy + r * 8];
        __nv_bfloat16 hb = __float2bfloat16(v);
        float rr = v - __bfloat162float(hb);
        size_t o = (size_t)blockIdx.z * HDIM * DMODEL + (size_t)n * DMODEL + k;
        g_wthi[o] = hb;
        g_wtlo[o] = __float2bfloat16(rr);
    }
}

// ============================================================================
// QKV projection GEMM via HMMA split-bf16.
// BM=64, N=128 full, K=512 in chunks of 64; 128 thr (4 warps, 16 rows/warp).
// Epilogue: +bias, (Q: * 1/sqrt(H)), split to bf16 hi/lo outputs.
// ============================================================================
#define XLD 72                                // smem row stride (bf16)
#define GX_B   (64  * XLD * 2)                //  9216 B per X tile
#define GW_B   (128 * XLD * 2)                // 18432 B per W tile
#define GSM_XH 0
#define GSM_XL (GSM_XH + GX_B)
#define GSM_WH (GSM_XL + GX_B)
#define GSM_WL (GSM_WH + GW_B)
#define GSM_TOTAL (GSM_WL + GW_B)             // 55296 B

__global__ __launch_bounds__(128) void qkv_hmma_kernel(
    const float* __restrict__ bq, const float* __restrict__ bk, const float* __restrict__ bv)
{
    extern __shared__ char sg[];
    const uint32_t uXH = smem_u32(sg) + GSM_XH;
    const uint32_t uXL = smem_u32(sg) + GSM_XL;
    const uint32_t uWH = smem_u32(sg) + GSM_WH;
    const uint32_t uWL = smem_u32(sg) + GSM_WL;

    const int tid  = threadIdx.x;
    const int w    = tid >> 5;
    const int lane = tid & 31;
    const int m0   = blockIdx.x * 64;
    const int y    = blockIdx.y;

    const __nv_bfloat16* wth = g_wthi + (size_t)y * HDIM * DMODEL;
    const __nv_bfloat16* wtl = g_wtlo + (size_t)y * HDIM * DMODEL;
    const float* bias = (y == 0) ? bq : (y == 1) ? bk : bv;

    float c[16][4];
#pragma unroll
    for (int j = 0; j < 16; j++)
#pragma unroll
        for (int q = 0; q < 4; q++) c[j][q] = 0.f;

    const int rowA = 16 * w + (lane & 15);
    const int colA = (lane >> 4) * 8;
    const int rowK = lane & 7;
    const int colK = ((lane >> 3) & 1) * 8;

    for (int k0 = 0; k0 < DMODEL; k0 += 64) {
        // X chunk: 64 rows x 64 cols (hi+lo)
#pragma unroll
        for (int it = 0; it < 4; it++) {
            int idx = tid + it * 128;
            int r = idx >> 3, cc = idx & 7;
            size_t go = (size_t)(m0 + r) * DMODEL + k0 + cc * 8;
            uint32_t so = (uint32_t)(r * XLD + cc * 8) * 2;
            cp16(uXH + so, g_xhi + go);
            cp16(uXL + so, g_xlo + go);
        }
        // Wt chunk: 128 rows x 64 cols (hi+lo)
#pragma unroll
        for (int it = 0; it < 8; it++) {
            int idx = tid + it * 128;
            int r = idx >> 3, cc = idx & 7;
            size_t go = (size_t)r * DMODEL + k0 + cc * 8;
            uint32_t so = (uint32_t)(r * XLD + cc * 8) * 2;
            cp16(uWH + so, wth + go);
            cp16(uWL + so, wtl + go);
        }
        cp_commit_wait();
        __syncthreads();

#pragma unroll
        for (int kc = 0; kc < 4; kc++) {
            uint32_t ah[4], al[4];
            uint32_t aoff = (uint32_t)(rowA * XLD + kc * 16 + colA) * 2;
            ldmx4(ah, uXH + aoff);
            ldmx4(al, uXL + aoff);
#pragma unroll
            for (int jn = 0; jn < 16; jn++) {
                uint32_t bh0, bh1, bl0, bl1;
                uint32_t off = (uint32_t)((8 * jn + rowK) * XLD + kc * 16 + colK) * 2;
                ldmx2(bh0, bh1, uWH + off);
                ldmx2(bl0, bl1, uWL + off);
                mma_bf16(c[jn], ah, bh0, bh1);
                mma_bf16(c[jn], ah, bl0, bl1);
                mma_bf16(c[jn], al, bh0, bh1);
            }
        }
        __syncthreads();
    }

    // epilogue
    const float sc = (y == 0) ? 0.08838834764831845f : 1.0f;   // 1/sqrt(128) into Q
    __nv_bfloat16* hiA = (y == 0) ? g_qhi : (y == 1) ? g_khi : g_vhi;
    __nv_bfloat16* loA = (y == 0) ? g_qlo : (y == 1) ? g_klo : g_vlo;
    const int grp = lane >> 2;
    const int tic = lane & 3;
    const int r0 = m0 + 16 * w + grp;
    const int r1 = r0 + 8;

#pragma unroll
    for (int jn = 0; jn < 16; jn++) {
        int n = 8 * jn + 2 * tic;
        float2 bo = *(const float2*)(bias + n);
        float o0 = (c[jn][0] + bo.x) * sc;
        float o1 = (c[jn][1] + bo.y) * sc;
        float o2 = (c[jn][2] + bo.x) * sc;
        float o3 = (c[jn][3] + bo.y) * sc;
        uint32_t h0 = packbf2(o0, o1);
        uint32_t h1 = packbf2(o2, o3);
        *(uint32_t*)&hiA[(size_t)r0 * HDIM + n] = h0;
        *(uint32_t*)&hiA[(size_t)r1 * HDIM + n] = h1;
        *(uint32_t*)&loA[(size_t)r0 * HDIM + n] = packbf2(o0 - bflo(h0), o1 - bfhi(h0));
        *(uint32_t*)&loA[(size_t)r1 * HDIM + n] = packbf2(o2 - bflo(h1), o3 - bfhi(h1));
    }
}

// ============================================================================
// FA2-style flash attention (causal), split-bf16 HMMA.
// BM=BN=64, 128 threads (4 warps); warp w owns q-rows 16w..16w+15.
// Q kept in SMEM (A-frags re-extracted per kc) -> ~180 regs, 2 CTAs/SM.
// ============================================================================
#define LDT 136                         // smem row stride in bf16 (272B)
#define TILE_B (64 * LDT * 2)           // 17408 bytes per tile
#define ASM_QHI 0
#define ASM_QLO (ASM_QHI + TILE_B)
#define ASM_KHI (ASM_QLO + TILE_B)
#define ASM_KLO (ASM_KHI + TILE_B)
#define ASM_VHI (ASM_KLO + TILE_B)
#define ASM_VLO (ASM_VHI + TILE_B)
#define ASM_TOTAL (ASM_VLO + TILE_B)    // 104448 bytes

__global__ __launch_bounds__(128, 2) void attn_kernel(float* __restrict__ out)
{
    extern __shared__ char smem[];
    const uint32_t uQHI = smem_u32(smem) + ASM_QHI;
    const uint32_t uQLO = smem_u32(smem) + ASM_QLO;
    const uint32_t uKHI = smem_u32(smem) + ASM_KHI;
    const uint32_t uKLO = smem_u32(smem) + ASM_KLO;
    const uint32_t uVHI = smem_u32(smem) + ASM_VHI;
    const uint32_t uVLO = smem_u32(smem) + ASM_VLO;

    const int tid  = threadIdx.x;
    const int w    = tid >> 5;
    const int lane = tid & 31;
    const int b    = blockIdx.y;
    const int qt   = (int)(gridDim.x - 1) - (int)blockIdx.x;   // heavy tiles first
    const int q0   = qt * 64;

    const int grp  = lane >> 2;
    const int tic  = lane & 3;
    const int qr0  = q0 + 16 * w + grp;
    const int qr1  = qr0 + 8;

    // ---- stage Q tile hi/lo into smem (persists across kt loop) ----
    {
        const __nv_bfloat16* qh = g_qhi + ((size_t)b * T_SEQ + q0) * HDIM;
        const __nv_bfloat16* ql = g_qlo + ((size_t)b * T_SEQ + q0) * HDIM;
#pragma unroll
        for (int it = 0; it < 8; it++) {
            int idx = tid + it * 128;
            int r = idx >> 4, cc = idx & 15;
            uint32_t so = (uint32_t)(r * LDT + cc * 8) * 2;
            cp16(uQHI + so, qh + (size_t)r * HDIM + cc * 8);
            cp16(uQLO + so, ql + (size_t)r * HDIM + cc * 8);
        }
        cp_commit_wait();
    }

    float O[16][4];
#pragma unroll
    for (int j = 0; j < 16; j++)
#pragma unroll
        for (int q = 0; q < 4; q++) O[j][q] = 0.f;
    float m0 = -1e30f, m1 = -1e30f, l0 = 0.f, l1 = 0.f;

    const int rowA = 16 * w + (lane & 15);
    const int colA = (lane >> 4) * 8;
    const int rowK = lane & 7;
    const int colK = ((lane >> 3) & 1) * 8;
    const int rowV = lane & 15;

    const __nv_bfloat16* kh = g_khi + (size_t)b * T_SEQ * HDIM;
    const __nv_bfloat16* kl = g_klo + (size_t)b * T_SEQ * HDIM;
    const __nv_bfloat16* vh = g_vhi + (size_t)b * T_SEQ * HDIM;
    const __nv_bfloat16* vl = g_vlo + (size_t)b * T_SEQ * HDIM;

    for (int kt = 0; kt <= qt; kt++) {
        const int kb = kt * 64;

        // ---- load K/V hi/lo tiles via cp.async ----
#pragma unroll
        for (int it = 0; it < 8; it++) {
            int idx = tid + it * 128;
            int r = idx >> 4, cc = idx & 15;
            size_t go = (size_t)(kb + r) * HDIM + cc * 8;
            uint32_t so = (uint32_t)(r * LDT + cc * 8) * 2;
            cp16(uKHI + so, kh + go);
            cp16(uKLO + so, kl + go);
            cp16(uVHI + so, vh + go);
            cp16(uVLO + so, vl + go);
        }
        cp_commit_wait();
        __syncthreads();

        // ---- S = Q K^T (split chain), A frags from smem per kc ----
        float s[8][4];
#pragma unroll
        for (int j = 0; j < 8; j++)
#pragma unroll
            for (int q = 0; q < 4; q++) s[j][q] = 0.f;

#pragma unroll
        for (int kc = 0; kc < 8; kc++) {
            uint32_t ah[4], al[4];
            uint32_t aoff = (uint32_t)(rowA * LDT + kc * 16 + colA) * 2;
            ldmx4(ah, uQHI + aoff);
            ldmx4(al, uQLO + aoff);
#pragma unroll
            for (int j = 0; j < 8; j++) {
                uint32_t bh0, bh1, bl0, bl1;
                uint32_t off = (uint32_t)((8 * j + rowK) * LDT + kc * 16 + colK) * 2;
                ldmx2(bh0, bh1, uKHI + off);
                ldmx2(bl0, bl1, uKLO + off);
                mma_bf16(s[j], ah, bh0, bh1);
                mma_bf16(s[j], ah, bl0, bl1);
                mma_bf16(s[j], al, bh0, bh1);
            }
        }

        // ---- causal mask (diag tile only) ----
        if (kt == qt) {
            const int cb = kb + 2 * tic;
#pragma unroll
            for (int j = 0; j < 8; j++) {
                int c0 = cb + 8 * j, c1 = c0 + 1;
                if (c0 > qr0) s[j][0] = -1e30f;
                if (c1 > qr0) s[j][1] = -1e30f;
                if (c0 > qr1) s[j][2] = -1e30f;
                if (c1 > qr1) s[j][3] = -1e30f;
            }
        }

        // ---- online softmax (rows live in 4-lane groups) ----
        float mx0 = -1e30f, mx1 = -1e30f;
#pragma unroll
        for (int j = 0; j < 8; j++) {
            mx0 = fmaxf(mx0, fmaxf(s[j][0], s[j][1]));
            mx1 = fmaxf(mx1, fmaxf(s[j][2], s[j][3]));
        }
        mx0 = fmaxf(mx0, __shfl_xor_sync(0xffffffffu, mx0, 1));
        mx0 = fmaxf(mx0, __shfl_xor_sync(0xffffffffu, mx0, 2));
        mx1 = fmaxf(mx1, __shfl_xor_sync(0xffffffffu, mx1, 1));
        mx1 = fmaxf(mx1, __shfl_xor_sync(0xffffffffu, mx1, 2));
        const float mn0 = fmaxf(m0, mx0);
        const float mn1 = fmaxf(m1, mx1);
        const float al0 = __expf(m0 - mn0);
        const float al1 = __expf(m1 - mn1);
        m0 = mn0; m1 = mn1;

        uint32_t phi[8][2], plo[8][2];
        float la0 = 0.f, la1 = 0.f;
#pragma unroll
        for (int j = 0; j < 8; j++) {
            float p0 = __expf(s[j][0] - mn0);
            float p1 = __expf(s[j][1] - mn0);
            float p2 = __expf(s[j][2] - mn1);
            float p3 = __expf(s[j][3] - mn1);
            la0 += p0 + p1; la1 += p2 + p3;
            uint32_t h0 = packbf2(p0, p1);
            uint32_t h1 = packbf2(p2, p3);
            phi[j][0] = h0; phi[j][1] = h1;
            plo[j][0] = packbf2(p0 - bflo(h0), p1 - bfhi(h0));
            plo[j][1] = packbf2(p2 - bflo(h1), p3 - bfhi(h1));
        }
        la0 += __shfl_xor_sync(0xffffffffu, la0, 1);
        la0 += __shfl_xor_sync(0xffffffffu, la0, 2);
        la1 += __shfl_xor_sync(0xffffffffu, la1, 1);
        la1 += __shfl_xor_sync(0xffffffffu, la1, 2);
        l0 = l0 * al0 + la0;
        l1 = l1 * al1 + la1;

#pragma unroll
        for (int j = 0; j < 16; j++) {
            O[j][0] *= al0; O[j][1] *= al0;
            O[j][2] *= al1; O[j][3] *= al1;
        }

        // ---- O += P V (split chain), A frags from P registers ----
#pragma unroll
        for (int kc = 0; kc < 4; kc++) {
            uint32_t ah[4] = { phi[2 * kc][0], phi[2 * kc][1], phi[2 * kc + 1][0], phi[2 * kc + 1][1] };
            uint32_t al[4] = { plo[2 * kc][0], plo[2 * kc][1], plo[2 * kc + 1][0], plo[2 * kc + 1][1] };
            const uint32_t offk = (uint32_t)((16 * kc + rowV) * LDT) * 2;
#pragma unroll
            for (int jn = 0; jn < 16; jn++) {
                uint32_t vh0, vh1, vl0, vl1;
                uint32_t off = offk + (uint32_t)(8 * jn) * 2;
                ldmx2t(vh0, vh1, uVHI + off);
                ldmx2t(vl0, vl1, uVLO + off);
                mma_bf16(O[jn], ah, vh0, vh1);
                mma_bf16(O[jn], ah, vl0, vl1);
                mma_bf16(O[jn], al, vh0, vh1);
            }
        }
        __syncthreads();   // smem tiles reused next iteration
    }

    // ---- epilogue: O / l ----
    const float i0 = 1.f / l0;
    const float i1 = 1.f / l1;
    float* o0 = out + ((size_t)b * T_SEQ + qr0) * HDIM;
    float* o1 = out + ((size_t)b * T_SEQ + qr1) * HDIM;
#pragma unroll
    for (int jn = 0; jn < 16; jn++) {
        int col = 8 * jn + 2 * tic;
        *(float2*)(o0 + col) = make_float2(O[jn][0] * i0, O[jn][1] * i0);
        *(float2*)(o1 + col) = make_float2(O[jn][2] * i1, O[jn][3] * i1);
    }
}

// ============================================================================
// launch
// ============================================================================
extern "C" void kernel_launch(void* const* d_in, const int* in_sizes, int n_in,
                              void* d_out, int out_size)
{
    (void)in_sizes; (void)n_in; (void)out_size;
    const float* x  = (const float*)d_in[0];
    // d_in[1] = mask (int32 causal tril) -- causality applied analytically
    const float* wq = (const float*)d_in[2];
    const float* bq = (const float*)d_in[3];
    const float* wk = (const float*)d_in[4];
    const float* bk = (const float*)d_in[5];
    const float* wv = (const float*)d_in[6];
    const float* bv = (const float*)d_in[7];
    float* out = (float*)d_out;

    split_x_kernel<<<M_ROWS * DMODEL / 4 / 256, 256>>>(x);

    dim3 gw(DMODEL / 32, HDIM / 32, 3);
    w_split_kernel<<<gw, 256>>>(wq, wk, wv);

    cudaFuncSetAttribute(qkv_hmma_kernel, cudaFuncAttributeMaxDynamicSharedMemorySize, GSM_TOTAL);
    dim3 gg(M_ROWS / 64, 3);
    qkv_hmma_kernel<<<gg, 128, GSM_TOTAL>>>(bq, bk, bv);

    cudaFuncSetAttribute(attn_kernel, cudaFuncAttributeMaxDynamicSharedMemorySize, ASM_TOTAL);
    dim3 ga(T_SEQ / 64, BATCH);
    attn_kernel<<<ga, 128, ASM_TOTAL>>>(out);
}

// round 10
// speedup vs baseline: 4.6802x; 1.1287x over previous
#include <cuda_runtime.h>
#include <cuda_bf16.h>
#include <math.h>
#include <stdint.h>

// Problem constants
#define BATCH   4
#define T_SEQ   4096
#define DMODEL  512
#define HDIM    128
#define M_ROWS  (BATCH * T_SEQ)   // 16384
#define NQT     (T_SEQ / 64)      // 64 q-tiles per batch
#define NJOBS   (BATCH * NQT * 2) // 512 split jobs

// pack two floats to bf16x2 word: lo 16 bits = first arg
__device__ __forceinline__ uint32_t packbf2(float lo, float hi) {
    uint32_t r;
    asm("cvt.rn.satfinite.bf16x2.f32 %0, %1, %2;" : "=r"(r) : "f"(hi), "f"(lo));
    return r;
}
__device__ __forceinline__ float bflo(uint32_t w) { return __uint_as_float(w << 16); }
__device__ __forceinline__ float bfhi(uint32_t w) { return __uint_as_float(w & 0xffff0000u); }

// ---------------- scratch (device globals: allocation-free) ----------------
__device__ __nv_bfloat16 g_xhi[M_ROWS * DMODEL];
__device__ __nv_bfloat16 g_xlo[M_ROWS * DMODEL];
__device__ __nv_bfloat16 g_wthi[3 * HDIM * DMODEL];   // W^T [y][n][k]
__device__ __nv_bfloat16 g_wtlo[3 * HDIM * DMODEL];
__device__ __nv_bfloat16 g_qhi[M_ROWS * HDIM];
__device__ __nv_bfloat16 g_qlo[M_ROWS * HDIM];
__device__ __nv_bfloat16 g_khi[M_ROWS * HDIM];
__device__ __nv_bfloat16 g_klo[M_ROWS * HDIM];
__device__ __nv_bfloat16 g_vhi[M_ROWS * HDIM];
__device__ __nv_bfloat16 g_vlo[M_ROWS * HDIM];
// KV-split partials
__device__ float g_pO[(size_t)NJOBS * 64 * HDIM];     // raw (unnormalized) O
__device__ float g_pm[NJOBS * 64];
__device__ float g_pl[NJOBS * 64];

// ---------------- mma / ldmatrix / cp.async helpers (base-target ISA) -------
__device__ __forceinline__ uint32_t smem_u32(const void* p) {
    uint32_t a;
    asm("{ .reg .u64 t; cvta.to.shared.u64 t, %1; cvt.u32.u64 %0, t; }" : "=r"(a) : "l"(p));
    return a;
}
__device__ __forceinline__ void mma_bf16(float* c, const uint32_t* a, uint32_t b0, uint32_t b1) {
    asm volatile(
        "mma.sync.aligned.m16n8k16.row.col.f32.bf16.bf16.f32 "
        "{%0,%1,%2,%3},{%4,%5,%6,%7},{%8,%9},{%0,%1,%2,%3};"
        : "+f"(c[0]), "+f"(c[1]), "+f"(c[2]), "+f"(c[3])
        : "r"(a[0]), "r"(a[1]), "r"(a[2]), "r"(a[3]), "r"(b0), "r"(b1));
}
__device__ __forceinline__ void ldmx4(uint32_t* r, uint32_t addr) {
    asm volatile("ldmatrix.sync.aligned.m8n8.x4.shared.b16 {%0,%1,%2,%3}, [%4];"
                 : "=r"(r[0]), "=r"(r[1]), "=r"(r[2]), "=r"(r[3]) : "r"(addr));
}
__device__ __forceinline__ void ldmx2(uint32_t& r0, uint32_t& r1, uint32_t addr) {
    asm volatile("ldmatrix.sync.aligned.m8n8.x2.shared.b16 {%0,%1}, [%2];"
                 : "=r"(r0), "=r"(r1) : "r"(addr));
}
__device__ __forceinline__ void ldmx2t(uint32_t& r0, uint32_t& r1, uint32_t addr) {
    asm volatile("ldmatrix.sync.aligned.m8n8.x2.trans.shared.b16 {%0,%1}, [%2];"
                 : "=r"(r0), "=r"(r1) : "r"(addr));
}
__device__ __forceinline__ void cp16(uint32_t dst, const void* src) {
    asm volatile("cp.async.cg.shared.global [%0], [%1], 16;" :: "r"(dst), "l"(src) : "memory");
}
__device__ __forceinline__ void cp_commit() {
    asm volatile("cp.async.commit_group;" ::: "memory");
}
__device__ __forceinline__ void cp_wait0() {
    asm volatile("cp.async.wait_group 0;" ::: "memory");
}
__device__ __forceinline__ void cp_wait1() {
    asm volatile("cp.async.wait_group 1;" ::: "memory");
}

// ============================================================================
// Prep 1: split x (fp32) -> bf16 hi/lo
// ============================================================================
__global__ __launch_bounds__(256) void split_x_kernel(const float* __restrict__ x)
{
    const int idx = blockIdx.x * 256 + threadIdx.x;     // float4 index
    float4 v = ((const float4*)x)[idx];
    uint32_t h0 = packbf2(v.x, v.y);
    uint32_t h1 = packbf2(v.z, v.w);
    float r0 = v.x - bflo(h0), r1 = v.y - bfhi(h0);
    float r2 = v.z - bflo(h1), r3 = v.w - bfhi(h1);
    *(uint2*)&g_xhi[(size_t)idx * 4] = make_uint2(h0, h1);
    *(uint2*)&g_xlo[(size_t)idx * 4] = make_uint2(packbf2(r0, r1), packbf2(r2, r3));
}

// ============================================================================
// Prep 2: transpose + split W [K=512][N=128] -> Wt [N][K] bf16 hi/lo, 3 mats
// ============================================================================
__global__ __launch_bounds__(256) void w_split_kernel(
    const float* __restrict__ wq, const float* __restrict__ wk, const float* __restrict__ wv)
{
    __shared__ float ts[32][33];
    const float* W = (blockIdx.z == 0) ? wq : (blockIdx.z == 1) ? wk : wv;
    const int k0 = blockIdx.x * 32;
    const int n0 = blockIdx.y * 32;
    const int txx = threadIdx.x & 31;
    const int tyy = threadIdx.x >> 5;   // 0..7
#pragma unroll
    for (int r = 0; r < 4; r++)
        ts[tyy + r * 8][txx] = W[(size_t)(k0 + tyy + r * 8) * HDIM + n0 + txx];
    __syncthreads();
#pragma unroll
    for (int r = 0; r < 4; r++) {
        int n = n0 + tyy + r * 8;
        int k = k0 + txx;
        float v = ts[txx][tyy + r * 8];
        __nv_bfloat16 hb = __float2bfloat16(v);
        float rr = v - __bfloat162float(hb);
        size_t o = (size_t)blockIdx.z * HDIM * DMODEL + (size_t)n * DMODEL + k;
        g_wthi[o] = hb;
        g_wtlo[o] = __float2bfloat16(rr);
    }
}

// ============================================================================
// QKV projection GEMM via HMMA split-bf16, 2-stage double buffer.
// BM=64, N=128 full, K=512 in chunks of 64; 128 thr (4 warps, 16 rows/warp).
// ============================================================================
#define XLD 72                                // smem row stride (bf16)
#define GX_B   (64  * XLD * 2)                //  9216 B per X tile
#define GW_B   (128 * XLD * 2)                // 18432 B per W tile
#define GSM_XH 0
#define GSM_XL (GSM_XH + GX_B)
#define GSM_WH (GSM_XL + GX_B)
#define GSM_WL (GSM_WH + GW_B)
#define GSTG   (GSM_WL + GW_B)                // 55296 B per stage
#define GSM_TOTAL (2 * GSTG)                  // 110592 B

__global__ __launch_bounds__(128, 2) void qkv_hmma_kernel(
    const float* __restrict__ bq, const float* __restrict__ bk, const float* __restrict__ bv)
{
    extern __shared__ char sg[];
    const uint32_t base = smem_u32(sg);

    const int tid  = threadIdx.x;
    const int w    = tid >> 5;
    const int lane = tid & 31;
    const int m0   = blockIdx.x * 64;
    const int y    = blockIdx.y;

    const __nv_bfloat16* wth = g_wthi + (size_t)y * HDIM * DMODEL;
    const __nv_bfloat16* wtl = g_wtlo + (size_t)y * HDIM * DMODEL;
    const float* bias = (y == 0) ? bq : (y == 1) ? bk : bv;

    float c[16][4];
#pragma unroll
    for (int j = 0; j < 16; j++)
#pragma unroll
        for (int q = 0; q < 4; q++) c[j][q] = 0.f;

    const int rowA = 16 * w + (lane & 15);
    const int colA = (lane >> 4) * 8;
    const int rowK = lane & 7;
    const int colK = ((lane >> 3) & 1) * 8;

    // issue loads for chunk cidx into stage
    auto issue = [&](int cidx, int stage) {
        const int k0 = cidx * 64;
        const uint32_t uXH = base + stage * GSTG + GSM_XH;
        const uint32_t uXL = base + stage * GSTG + GSM_XL;
        const uint32_t uWH = base + stage * GSTG + GSM_WH;
        const uint32_t uWL = base + stage * GSTG + GSM_WL;
#pragma unroll
        for (int it = 0; it < 4; it++) {
            int idx = tid + it * 128;
            int r = idx >> 3, cc = idx & 7;
            size_t go = (size_t)(m0 + r) * DMODEL + k0 + cc * 8;
            uint32_t so = (uint32_t)(r * XLD + cc * 8) * 2;
            cp16(uXH + so, g_xhi + go);
            cp16(uXL + so, g_xlo + go);
        }
#pragma unroll
        for (int it = 0; it < 8; it++) {
            int idx = tid + it * 128;
            int r = idx >> 3, cc = idx & 7;
            size_t go = (size_t)r * DMODEL + k0 + cc * 8;
            uint32_t so = (uint32_t)(r * XLD + cc * 8) * 2;
            cp16(uWH + so, wth + go);
            cp16(uWL + so, wtl + go);
        }
        cp_commit();
    };

    issue(0, 0);
    for (int cidx = 0; cidx < DMODEL / 64; cidx++) {
        const int stage = cidx & 1;
        if (cidx + 1 < DMODEL / 64) {
            issue(cidx + 1, stage ^ 1);
            cp_wait1();
        } else {
            cp_wait0();
        }
        __syncthreads();

        const uint32_t uXH = base + stage * GSTG + GSM_XH;
        const uint32_t uXL = base + stage * GSTG + GSM_XL;
        const uint32_t uWH = base + stage * GSTG + GSM_WH;
        const uint32_t uWL = base + stage * GSTG + GSM_WL;
#pragma unroll
        for (int kc = 0; kc < 4; kc++) {
            uint32_t ah[4], al[4];
            uint32_t aoff = (uint32_t)(rowA * XLD + kc * 16 + colA) * 2;
            ldmx4(ah, uXH + aoff);
            ldmx4(al, uXL + aoff);
#pragma unroll
            for (int jn = 0; jn < 16; jn++) {
                uint32_t bh0, bh1, bl0, bl1;
                uint32_t off = (uint32_t)((8 * jn + rowK) * XLD + kc * 16 + colK) * 2;
                ldmx2(bh0, bh1, uWH + off);
                ldmx2(bl0, bl1, uWL + off);
                mma_bf16(c[jn], ah, bh0, bh1);
                mma_bf16(c[jn], ah, bl0, bl1);
                mma_bf16(c[jn], al, bh0, bh1);
            }
        }
        __syncthreads();
    }

    // epilogue
    const float sc = (y == 0) ? 0.08838834764831845f : 1.0f;   // 1/sqrt(128) into Q
    __nv_bfloat16* hiA = (y == 0) ? g_qhi : (y == 1) ? g_khi : g_vhi;
    __nv_bfloat16* loA = (y == 0) ? g_qlo : (y == 1) ? g_klo : g_vlo;
    const int grp = lane >> 2;
    const int tic = lane & 3;
    const int r0 = m0 + 16 * w + grp;
    const int r1 = r0 + 8;

#pragma unroll
    for (int jn = 0; jn < 16; jn++) {
        int n = 8 * jn + 2 * tic;
        float2 bo = *(const float2*)(bias + n);
        float o0 = (c[jn][0] + bo.x) * sc;
        float o1 = (c[jn][1] + bo.y) * sc;
        float o2 = (c[jn][2] + bo.x) * sc;
        float o3 = (c[jn][3] + bo.y) * sc;
        uint32_t h0 = packbf2(o0, o1);
        uint32_t h1 = packbf2(o2, o3);
        *(uint32_t*)&hiA[(size_t)r0 * HDIM + n] = h0;
        *(uint32_t*)&hiA[(size_t)r1 * HDIM + n] = h1;
        *(uint32_t*)&loA[(size_t)r0 * HDIM + n] = packbf2(o0 - bflo(h0), o1 - bfhi(h0));
        *(uint32_t*)&loA[(size_t)r1 * HDIM + n] = packbf2(o2 - bflo(h1), o3 - bfhi(h1));
    }
}

// ============================================================================
// FA2-style flash attention (causal), split-bf16 HMMA, 2-way KV split.
// Block (qt, half): processes kt = half, half+2, ... <= qt with its own online
// softmax; writes raw partial (O, m, l). Deferred cp.async prefetch of next
// K (during softmax/PV) and next V (during next S) -- zero extra smem.
// ============================================================================
#define LDT 136                         // smem row stride in bf16 (272B)
#define TILE_B (64 * LDT * 2)           // 17408 bytes per tile
#define ASM_QHI 0
#define ASM_QLO (ASM_QHI + TILE_B)
#define ASM_KHI (ASM_QLO + TILE_B)
#define ASM_KLO (ASM_KHI + TILE_B)
#define ASM_VHI (ASM_KLO + TILE_B)
#define ASM_VLO (ASM_VHI + TILE_B)
#define ASM_TOTAL (ASM_VLO + TILE_B)    // 104448 bytes

__global__ __launch_bounds__(128, 2) void attn_kernel()
{
    extern __shared__ char smem[];
    const uint32_t uQHI = smem_u32(smem) + ASM_QHI;
    const uint32_t uQLO = smem_u32(smem) + ASM_QLO;
    const uint32_t uKHI = smem_u32(smem) + ASM_KHI;
    const uint32_t uKLO = smem_u32(smem) + ASM_KLO;
    const uint32_t uVHI = smem_u32(smem) + ASM_VHI;
    const uint32_t uVLO = smem_u32(smem) + ASM_VLO;

    const int tid  = threadIdx.x;
    const int w    = tid >> 5;
    const int lane = tid & 31;
    const int b    = blockIdx.y;
    const int qt   = NQT - 1 - ((int)blockIdx.x >> 1);   // heavy jobs first
    const int half = (int)blockIdx.x & 1;
    const int q0   = qt * 64;

    const int grp  = lane >> 2;
    const int tic  = lane & 3;
    const int rl0  = 16 * w + grp;        // local row within tile
    const int rl1  = rl0 + 8;
    const int qr0  = q0 + rl0;
    const int qr1  = q0 + rl1;

    const __nv_bfloat16* kh = g_khi + (size_t)b * T_SEQ * HDIM;
    const __nv_bfloat16* kl = g_klo + (size_t)b * T_SEQ * HDIM;
    const __nv_bfloat16* vh = g_vhi + (size_t)b * T_SEQ * HDIM;
    const __nv_bfloat16* vl = g_vlo + (size_t)b * T_SEQ * HDIM;

    auto issueK = [&](int kt_) {
        const int kb = kt_ * 64;
#pragma unroll
        for (int it = 0; it < 8; it++) {
            int idx = tid + it * 128;
            int r = idx >> 4, cc = idx & 15;
            size_t go = (size_t)(kb + r) * HDIM + cc * 8;
            uint32_t so = (uint32_t)(r * LDT + cc * 8) * 2;
            cp16(uKHI + so, kh + go);
            cp16(uKLO + so, kl + go);
        }
        cp_commit();
    };
    auto issueV = [&](int kt_) {
        const int kb = kt_ * 64;
#pragma unroll
        for (int it = 0; it < 8; it++) {
            int idx = tid + it * 128;
            int r = idx >> 4, cc = idx & 15;
            size_t go = (size_t)(kb + r) * HDIM + cc * 8;
            uint32_t so = (uint32_t)(r * LDT + cc * 8) * 2;
            cp16(uVHI + so, vh + go);
            cp16(uVLO + so, vl + go);
        }
        cp_commit();
    };

    float O[16][4];
#pragma unroll
    for (int j = 0; j < 16; j++)
#pragma unroll
        for (int q = 0; q < 4; q++) O[j][q] = 0.f;
    float m0 = -1e30f, m1 = -1e30f, l0 = 0.f, l1 = 0.f;

    const int rowA = 16 * w + (lane & 15);
    const int colA = (lane >> 4) * 8;
    const int rowK = lane & 7;
    const int colK = ((lane >> 3) & 1) * 8;
    const int rowV = lane & 15;

    const int kt0 = half;
    if (kt0 <= qt) {
        // ---- stage Q tile hi/lo into smem (persists) + preload K,V ----
        {
            const __nv_bfloat16* qh = g_qhi + ((size_t)b * T_SEQ + q0) * HDIM;
            const __nv_bfloat16* ql = g_qlo + ((size_t)b * T_SEQ + q0) * HDIM;
#pragma unroll
            for (int it = 0; it < 8; it++) {
                int idx = tid + it * 128;
                int r = idx >> 4, cc = idx & 15;
                uint32_t so = (uint32_t)(r * LDT + cc * 8) * 2;
                cp16(uQHI + so, qh + (size_t)r * HDIM + cc * 8);
                cp16(uQLO + so, ql + (size_t)r * HDIM + cc * 8);
            }
            cp_commit();
        }
        issueK(kt0);
        issueV(kt0);
        cp_wait0();
        __syncthreads();

        for (int kt = kt0; kt <= qt; kt += 2) {
            const bool has_next = (kt + 2 <= qt);
            const int kb = kt * 64;

            // ---- S = Q K^T (split chain, dual accumulators) ----
            float s_hh[8][4], s_x[8][4];
#pragma unroll
            for (int j = 0; j < 8; j++)
#pragma unroll
                for (int q = 0; q < 4; q++) { s_hh[j][q] = 0.f; s_x[j][q] = 0.f; }

#pragma unroll
            for (int kc = 0; kc < 8; kc++) {
                uint32_t ah[4], al[4];
                uint32_t aoff = (uint32_t)(rowA * LDT + kc * 16 + colA) * 2;
                ldmx4(ah, uQHI + aoff);
                ldmx4(al, uQLO + aoff);
#pragma unroll
                for (int j = 0; j < 8; j++) {
                    uint32_t bh0, bh1, bl0, bl1;
                    uint32_t off = (uint32_t)((8 * j + rowK) * LDT + kc * 16 + colK) * 2;
                    ldmx2(bh0, bh1, uKHI + off);
                    ldmx2(bl0, bl1, uKLO + off);
                    mma_bf16(s_hh[j], ah, bh0, bh1);
                    mma_bf16(s_x[j],  ah, bl0, bl1);
                    mma_bf16(s_x[j],  al, bh0, bh1);
                }
            }
            __syncthreads();                 // done reading K bufs
            if (has_next) issueK(kt + 2);    // K prefetch flies during softmax+PV

            // ---- combine + causal mask ----
            float s[8][4];
#pragma unroll
            for (int j = 0; j < 8; j++)
#pragma unroll
                for (int q = 0; q < 4; q++) s[j][q] = s_hh[j][q] + s_x[j][q];
            if (kt == qt) {
                const int cb = kb + 2 * tic;
#pragma unroll
                for (int j = 0; j < 8; j++) {
                    int c0 = cb + 8 * j, c1 = c0 + 1;
                    if (c0 > qr0) s[j][0] = -1e30f;
                    if (c1 > qr0) s[j][1] = -1e30f;
                    if (c0 > qr1) s[j][2] = -1e30f;
                    if (c1 > qr1) s[j][3] = -1e30f;
                }
            }

            // ---- online softmax ----
            float mx0 = -1e30f, mx1 = -1e30f;
#pragma unroll
            for (int j = 0; j < 8; j++) {
                mx0 = fmaxf(mx0, fmaxf(s[j][0], s[j][1]));
                mx1 = fmaxf(mx1, fmaxf(s[j][2], s[j][3]));
            }
            mx0 = fmaxf(mx0, __shfl_xor_sync(0xffffffffu, mx0, 1));
            mx0 = fmaxf(mx0, __shfl_xor_sync(0xffffffffu, mx0, 2));
            mx1 = fmaxf(mx1, __shfl_xor_sync(0xffffffffu, mx1, 1));
            mx1 = fmaxf(mx1, __shfl_xor_sync(0xffffffffu, mx1, 2));
            const float mn0 = fmaxf(m0, mx0);
            const float mn1 = fmaxf(m1, mx1);
            const float al0 = __expf(m0 - mn0);
            const float al1 = __expf(m1 - mn1);
            m0 = mn0; m1 = mn1;

            uint32_t phi[8][2], plo[8][2];
            float la0 = 0.f, la1 = 0.f;
#pragma unroll
            for (int j = 0; j < 8; j++) {
                float p0 = __expf(s[j][0] - mn0);
                float p1 = __expf(s[j][1] - mn0);
                float p2 = __expf(s[j][2] - mn1);
                float p3 = __expf(s[j][3] - mn1);
                la0 += p0 + p1; la1 += p2 + p3;
                uint32_t h0 = packbf2(p0, p1);
                uint32_t h1 = packbf2(p2, p3);
                phi[j][0] = h0; phi[j][1] = h1;
                plo[j][0] = packbf2(p0 - bflo(h0), p1 - bfhi(h0));
                plo[j][1] = packbf2(p2 - bflo(h1), p3 - bfhi(h1));
            }
            la0 += __shfl_xor_sync(0xffffffffu, la0, 1);
            la0 += __shfl_xor_sync(0xffffffffu, la0, 2);
            la1 += __shfl_xor_sync(0xffffffffu, la1, 1);
            la1 += __shfl_xor_sync(0xffffffffu, la1, 2);
            l0 = l0 * al0 + la0;
            l1 = l1 * al1 + la1;

#pragma unroll
            for (int j = 0; j < 16; j++) {
                O[j][0] *= al0; O[j][1] *= al0;
                O[j][2] *= al1; O[j][3] *= al1;
            }

            // V(kt) must be resident: for kt>kt0 its group may still fly
            if (kt > kt0) {
                if (has_next) cp_wait1(); else cp_wait0();
                __syncthreads();
            }

            // ---- O += P V (split chain), A frags from P registers ----
#pragma unroll
            for (int kc = 0; kc < 4; kc++) {
                uint32_t ah[4] = { phi[2*kc][0], phi[2*kc][1], phi[2*kc+1][0], phi[2*kc+1][1] };
                uint32_t al[4] = { plo[2*kc][0], plo[2*kc][1], plo[2*kc+1][0], plo[2*kc+1][1] };
                const uint32_t offk = (uint32_t)((16 * kc + rowV) * LDT) * 2;
#pragma unroll
                for (int jn = 0; jn < 16; jn++) {
                    uint32_t vh0, vh1, vl0, vl1;
                    uint32_t off = offk + (uint32_t)(8 * jn) * 2;
                    ldmx2t(vh0, vh1, uVHI + off);
                    ldmx2t(vl0, vl1, uVLO + off);
                    mma_bf16(O[jn], ah, vh0, vh1);
                    mma_bf16(O[jn], ah, vl0, vl1);
                    mma_bf16(O[jn], al, vh0, vh1);
                }
            }
            __syncthreads();                  // done reading V bufs
            if (has_next) {
                issueV(kt + 2);               // V prefetch flies during next S
                cp_wait1();                   // K(kt+2) resident (V still flying)
                __syncthreads();
            }
        }
    }

    // ---- epilogue: write raw partial (O, m, l) ----
    const size_t job = ((size_t)(b * NQT + qt) * 2 + half);
    float* pO = g_pO + job * 64 * HDIM;
    if (tic == 0) {
        g_pm[job * 64 + rl0] = m0;
        g_pl[job * 64 + rl0] = l0;
        g_pm[job * 64 + rl1] = m1;
        g_pl[job * 64 + rl1] = l1;
    }
#pragma unroll
    for (int jn = 0; jn < 16; jn++) {
        int col = 8 * jn + 2 * tic;
        *(float2*)(pO + (size_t)rl0 * HDIM + col) = make_float2(O[jn][0], O[jn][1]);
        *(float2*)(pO + (size_t)rl1 * HDIM + col) = make_float2(O[jn][2], O[jn][3]);
    }
}

// ============================================================================
// Merge: combine the two KV-split partials per q-row.
// grid (NQT, BATCH), 256 threads: row = tid>>2 (64 rows), 32 cols/thread.
// ============================================================================
__global__ __launch_bounds__(256) void merge_kernel(float* __restrict__ out)
{
    const int qt = blockIdx.x;
    const int b  = blockIdx.y;
    const int r  = threadIdx.x >> 2;         // 0..63
    const int cq = threadIdx.x & 3;          // col quarter
    const size_t j0 = ((size_t)(b * NQT + qt) * 2);

    const float m0 = g_pm[j0 * 64 + r];
    const float l0 = g_pl[j0 * 64 + r];
    const float m1 = g_pm[(j0 + 1) * 64 + r];
    const float l1 = g_pl[(j0 + 1) * 64 + r];
    const float M  = fmaxf(m0, m1);
    const float a0 = __expf(m0 - M);
    const float a1 = __expf(m1 - M);
    const float inv = 1.f / (a0 * l0 + a1 * l1);

    const float* p0 = g_pO + j0 * 64 * HDIM + (size_t)r * HDIM + cq * 32;
    const float* p1 = p0 + (size_t)64 * HDIM;
    float* orow = out + ((size_t)b * T_SEQ + qt * 64 + r) * HDIM + cq * 32;
#pragma unroll
    for (int c4 = 0; c4 < 8; c4++) {
        float4 v0 = *(const float4*)(p0 + c4 * 4);
        float4 v1 = *(const float4*)(p1 + c4 * 4);
        float4 o;
        o.x = (a0 * v0.x + a1 * v1.x) * inv;
        o.y = (a0 * v0.y + a1 * v1.y) * inv;
        o.z = (a0 * v0.z + a1 * v1.z) * inv;
        o.w = (a0 * v0.w + a1 * v1.w) * inv;
        *(float4*)(orow + c4 * 4) = o;
    }
}

// ============================================================================
// launch
// ============================================================================
extern "C" void kernel_launch(void* const* d_in, const int* in_sizes, int n_in,
                              void* d_out, int out_size)
{
    (void)in_sizes; (void)n_in; (void)out_size;
    const float* x  = (const float*)d_in[0];
    // d_in[1] = mask (int32 causal tril) -- causality applied analytically
    const float* wq = (const float*)d_in[2];
    const float* bq = (const float*)d_in[3];
    const float* wk = (const float*)d_in[4];
    const float* bk = (const float*)d_in[5];
    const float* wv = (const float*)d_in[6];
    const float* bv = (const float*)d_in[7];
    float* out = (float*)d_out;

    split_x_kernel<<<M_ROWS * DMODEL / 4 / 256, 256>>>(x);

    dim3 gw(DMODEL / 32, HDIM / 32, 3);
    w_split_kernel<<<gw, 256>>>(wq, wk, wv);

    cudaFuncSetAttribute(qkv_hmma_kernel, cudaFuncAttributeMaxDynamicSharedMemorySize, GSM_TOTAL);
    dim3 gg(M_ROWS / 64, 3);
    qkv_hmma_kernel<<<gg, 128, GSM_TOTAL>>>(bq, bk, bv);

    cudaFuncSetAttribute(attn_kernel, cudaFuncAttributeMaxDynamicSharedMemorySize, ASM_TOTAL);
    dim3 ga(2 * NQT, BATCH);
    attn_kernel<<<ga, 128, ASM_TOTAL>>>();

    dim3 gm(NQT, BATCH);
    merge_kernel<<<gm, 256>>>(out);
}

// round 12
// speedup vs baseline: 5.5417x; 1.1841x over previous
#include <cuda_runtime.h>
#include <cuda_bf16.h>
#include <math.h>
#include <stdint.h>

// Problem constants
#define BATCH   4
#define T_SEQ   4096
#define DMODEL  512
#define HDIM    128
#define M_ROWS  (BATCH * T_SEQ)   // 16384
#define NQT     (T_SEQ / 64)      // 64 q-tiles per batch
#define NSPLIT  4                 // KV-split ways
#define NJOBS   (BATCH * NQT * NSPLIT)

// pack two floats to bf16x2 word: lo 16 bits = first arg
__device__ __forceinline__ uint32_t packbf2(float lo, float hi) {
    uint32_t r;
    asm("cvt.rn.satfinite.bf16x2.f32 %0, %1, %2;" : "=r"(r) : "f"(hi), "f"(lo));
    return r;
}
__device__ __forceinline__ float bflo(uint32_t w) { return __uint_as_float(w << 16); }
__device__ __forceinline__ float bfhi(uint32_t w) { return __uint_as_float(w & 0xffff0000u); }
__device__ __forceinline__ float ex2(float x) {
    float y;
    asm("ex2.approx.f32 %0, %1;" : "=f"(y) : "f"(x));
    return y;
}

// ---------------- scratch (device globals: allocation-free) ----------------
__device__ __nv_bfloat16 g_xhi[M_ROWS * DMODEL];
__device__ __nv_bfloat16 g_xlo[M_ROWS * DMODEL];
__device__ __nv_bfloat16 g_wthi[3 * HDIM * DMODEL];   // W^T [y][n][k]
__device__ __nv_bfloat16 g_wtlo[3 * HDIM * DMODEL];
__device__ __nv_bfloat16 g_qhi[M_ROWS * HDIM];
__device__ __nv_bfloat16 g_qlo[M_ROWS * HDIM];
__device__ __nv_bfloat16 g_khi[M_ROWS * HDIM];
__device__ __nv_bfloat16 g_klo[M_ROWS * HDIM];
__device__ __nv_bfloat16 g_vhi[M_ROWS * HDIM];
__device__ __nv_bfloat16 g_vlo[M_ROWS * HDIM];
// KV-split partials (zero-initialized device globals; empty jobs rely on 0s in g_pO)
__device__ float g_pO[(size_t)NJOBS * 64 * HDIM];     // raw (unnormalized) O
__device__ float g_pm[NJOBS * 64];                    // log2-domain running max
__device__ float g_pl[NJOBS * 64];

// ---------------- mma / ldmatrix / cp.async helpers (base-target ISA) -------
__device__ __forceinline__ uint32_t smem_u32(const void* p) {
    uint32_t a;
    asm("{ .reg .u64 t; cvta.to.shared.u64 t, %1; cvt.u32.u64 %0, t; }" : "=r"(a) : "l"(p));
    return a;
}
__device__ __forceinline__ void mma_bf16(float* c, const uint32_t* a, uint32_t b0, uint32_t b1) {
    asm volatile(
        "mma.sync.aligned.m16n8k16.row.col.f32.bf16.bf16.f32 "
        "{%0,%1,%2,%3},{%4,%5,%6,%7},{%8,%9},{%0,%1,%2,%3};"
        : "+f"(c[0]), "+f"(c[1]), "+f"(c[2]), "+f"(c[3])
        : "r"(a[0]), "r"(a[1]), "r"(a[2]), "r"(a[3]), "r"(b0), "r"(b1));
}
__device__ __forceinline__ void ldmx4(uint32_t* r, uint32_t addr) {
    asm volatile("ldmatrix.sync.aligned.m8n8.x4.shared.b16 {%0,%1,%2,%3}, [%4];"
                 : "=r"(r[0]), "=r"(r[1]), "=r"(r[2]), "=r"(r[3]) : "r"(addr));
}
__device__ __forceinline__ void ldmx4t(uint32_t* r, uint32_t addr) {
    asm volatile("ldmatrix.sync.aligned.m8n8.x4.trans.shared.b16 {%0,%1,%2,%3}, [%4];"
                 : "=r"(r[0]), "=r"(r[1]), "=r"(r[2]), "=r"(r[3]) : "r"(addr));
}
__device__ __forceinline__ void cp16(uint32_t dst, const void* src) {
    asm volatile("cp.async.cg.shared.global [%0], [%1], 16;" :: "r"(dst), "l"(src) : "memory");
}
__device__ __forceinline__ void cp_commit() {
    asm volatile("cp.async.commit_group;" ::: "memory");
}
__device__ __forceinline__ void cp_wait0() {
    asm volatile("cp.async.wait_group 0;" ::: "memory");
}
__device__ __forceinline__ void cp_wait1() {
    asm volatile("cp.async.wait_group 1;" ::: "memory");
}

// ============================================================================
// Prep 1: split x (fp32) -> bf16 hi/lo
// ============================================================================
__global__ __launch_bounds__(256) void split_x_kernel(const float* __restrict__ x)
{
    const int idx = blockIdx.x * 256 + threadIdx.x;     // float4 index
    float4 v = ((const float4*)x)[idx];
    uint32_t h0 = packbf2(v.x, v.y);
    uint32_t h1 = packbf2(v.z, v.w);
    float r0 = v.x - bflo(h0), r1 = v.y - bfhi(h0);
    float r2 = v.z - bflo(h1), r3 = v.w - bfhi(h1);
    *(uint2*)&g_xhi[(size_t)idx * 4] = make_uint2(h0, h1);
    *(uint2*)&g_xlo[(size_t)idx * 4] = make_uint2(packbf2(r0, r1), packbf2(r2, r3));
}

// ============================================================================
// Prep 2: transpose + split W [K=512][N=128] -> Wt [N][K] bf16 hi/lo, 3 mats
// ============================================================================
__global__ __launch_bounds__(256) void w_split_kernel(
    const float* __restrict__ wq, const float* __restrict__ wk, const float* __restrict__ wv)
{
    __shared__ float ts[32][33];
    const float* W = (blockIdx.z == 0) ? wq : (blockIdx.z == 1) ? wk : wv;
    const int k0 = blockIdx.x * 32;
    const int n0 = blockIdx.y * 32;
    const int txx = threadIdx.x & 31;
    const int tyy = threadIdx.x >> 5;   // 0..7
#pragma unroll
    for (int r = 0; r < 4; r++)
        ts[tyy + r * 8][txx] = W[(size_t)(k0 + tyy + r * 8) * HDIM + n0 + txx];
    __syncthreads();
#pragma unroll
    for (int r = 0; r < 4; r++) {
        int n = n0 + tyy + r * 8;
        int k = k0 + txx;
        float v = ts[txx][tyy + r * 8];
        __nv_bfloat16 hb = __float2bfloat16(v);
        float rr = v - __bfloat162float(hb);
        size_t o = (size_t)blockIdx.z * HDIM * DMODEL + (size_t)n * DMODEL + k;
        g_wthi[o] = hb;
        g_wtlo[o] = __float2bfloat16(rr);
    }
}

// ============================================================================
// QKV projection GEMM via HMMA split-bf16, 2-stage double buffer, x4 B loads.
// BM=64, N=128 full, K=512 in chunks of 64; 128 thr (4 warps, 16 rows/warp).
// ============================================================================
#define XLD 72                                // smem row stride (bf16)
#define GX_B   (64  * XLD * 2)                //  9216 B per X tile
#define GW_B   (128 * XLD * 2)                // 18432 B per W tile
#define GSM_XH 0
#define GSM_XL (GSM_XH + GX_B)
#define GSM_WH (GSM_XL + GX_B)
#define GSM_WL (GSM_WH + GW_B)
#define GSTG   (GSM_WL + GW_B)                // 55296 B per stage
#define GSM_TOTAL (2 * GSTG)                  // 110592 B

__global__ __launch_bounds__(128, 2) void qkv_hmma_kernel(
    const float* __restrict__ bq, const float* __restrict__ bk, const float* __restrict__ bv)
{
    extern __shared__ char sg[];
    const uint32_t base = smem_u32(sg);

    const int tid  = threadIdx.x;
    const int w    = tid >> 5;
    const int lane = tid & 31;
    const int m0   = blockIdx.x * 64;
    const int y    = blockIdx.y;

    const __nv_bfloat16* wth = g_wthi + (size_t)y * HDIM * DMODEL;
    const __nv_bfloat16* wtl = g_wtlo + (size_t)y * HDIM * DMODEL;
    const float* bias = (y == 0) ? bq : (y == 1) ? bk : bv;

    float c[16][4];
#pragma unroll
    for (int j = 0; j < 16; j++)
#pragma unroll
        for (int q = 0; q < 4; q++) c[j][q] = 0.f;

    const int rowA  = 16 * w + (lane & 15);
    const int colA  = (lane >> 4) * 8;
    const int rowB4 = ((lane >> 4) << 3) + (lane & 7);   // x4: row within jn-pair
    const int colB4 = ((lane >> 3) & 1) * 8;

    auto issue = [&](int cidx, int stage) {
        const int k0 = cidx * 64;
        const uint32_t uXH = base + stage * GSTG + GSM_XH;
        const uint32_t uXL = base + stage * GSTG + GSM_XL;
        const uint32_t uWH = base + stage * GSTG + GSM_WH;
        const uint32_t uWL = base + stage * GSTG + GSM_WL;
#pragma unroll
        for (int it = 0; it < 4; it++) {
            int idx = tid + it * 128;
            int r = idx >> 3, cc = idx & 7;
            size_t go = (size_t)(m0 + r) * DMODEL + k0 + cc * 8;
            uint32_t so = (uint32_t)(r * XLD + cc * 8) * 2;
            cp16(uXH + so, g_xhi + go);
            cp16(uXL + so, g_xlo + go);
        }
#pragma unroll
        for (int it = 0; it < 8; it++) {
            int idx = tid + it * 128;
            int r = idx >> 3, cc = idx & 7;
            size_t go = (size_t)r * DMODEL + k0 + cc * 8;
            uint32_t so = (uint32_t)(r * XLD + cc * 8) * 2;
            cp16(uWH + so, wth + go);
            cp16(uWL + so, wtl + go);
        }
        cp_commit();
    };

    issue(0, 0);
    for (int cidx = 0; cidx < DMODEL / 64; cidx++) {
        const int stage = cidx & 1;
        if (cidx + 1 < DMODEL / 64) {
            issue(cidx + 1, stage ^ 1);
            cp_wait1();
        } else {
            cp_wait0();
        }
        __syncthreads();

        const uint32_t uXH = base + stage * GSTG + GSM_XH;
        const uint32_t uXL = base + stage * GSTG + GSM_XL;
        const uint32_t uWH = base + stage * GSTG + GSM_WH;
        const uint32_t uWL = base + stage * GSTG + GSM_WL;
#pragma unroll
        for (int kc = 0; kc < 4; kc++) {
            uint32_t ah[4], al[4];
            uint32_t aoff = (uint32_t)(rowA * XLD + kc * 16 + colA) * 2;
            ldmx4(ah, uXH + aoff);
            ldmx4(al, uXL + aoff);
#pragma unroll
            for (int jp = 0; jp < 8; jp++) {
                const int jn = 2 * jp;
                uint32_t bh[4], bl[4];
                uint32_t off = (uint32_t)((8 * jn + rowB4) * XLD + kc * 16 + colB4) * 2;
                ldmx4(bh, uWH + off);
                ldmx4(bl, uWL + off);
                mma_bf16(c[jn],     ah, bh[0], bh[1]);
                mma_bf16(c[jn],     ah, bl[0], bl[1]);
                mma_bf16(c[jn],     al, bh[0], bh[1]);
                mma_bf16(c[jn + 1], ah, bh[2], bh[3]);
                mma_bf16(c[jn + 1], ah, bl[2], bl[3]);
                mma_bf16(c[jn + 1], al, bh[2], bh[3]);
            }
        }
        __syncthreads();
    }

    // epilogue: Q scale folds 1/sqrt(128) AND log2(e) for exp2-domain softmax
    const float sc = (y == 0) ? 0.12753297f : 1.0f;
    __nv_bfloat16* hiA = (y == 0) ? g_qhi : (y == 1) ? g_khi : g_vhi;
    __nv_bfloat16* loA = (y == 0) ? g_qlo : (y == 1) ? g_klo : g_vlo;
    const int grp = lane >> 2;
    const int tic = lane & 3;
    const int r0 = m0 + 16 * w + grp;
    const int r1 = r0 + 8;

#pragma unroll
    for (int jn = 0; jn < 16; jn++) {
        int n = 8 * jn + 2 * tic;
        float2 bo = *(const float2*)(bias + n);
        float o0 = (c[jn][0] + bo.x) * sc;
        float o1 = (c[jn][1] + bo.y) * sc;
        float o2 = (c[jn][2] + bo.x) * sc;
        float o3 = (c[jn][3] + bo.y) * sc;
        uint32_t h0 = packbf2(o0, o1);
        uint32_t h1 = packbf2(o2, o3);
        *(uint32_t*)&hiA[(size_t)r0 * HDIM + n] = h0;
        *(uint32_t*)&hiA[(size_t)r1 * HDIM + n] = h1;
        *(uint32_t*)&loA[(size_t)r0 * HDIM + n] = packbf2(o0 - bflo(h0), o1 - bfhi(h0));
        *(uint32_t*)&loA[(size_t)r1 * HDIM + n] = packbf2(o2 - bflo(h1), o3 - bfhi(h1));
    }
}

// ============================================================================
// FA2-style flash attention (causal), split-bf16 HMMA, 4-way KV split,
// exp2-domain softmax, x4 ldmatrix B-operand loads, deferred cp.async prefetch.
// Block (qt, half): kt = half, half+4, ... <= qt.
// ============================================================================
#define LDT 136                         // smem row stride in bf16 (272B)
#define TILE_B (64 * LDT * 2)           // 17408 bytes per tile
#define ASM_QHI 0
#define ASM_QLO (ASM_QHI + TILE_B)
#define ASM_KHI (ASM_QLO + TILE_B)
#define ASM_KLO (ASM_KHI + TILE_B)
#define ASM_VHI (ASM_KLO + TILE_B)
#define ASM_VLO (ASM_VHI + TILE_B)
#define ASM_TOTAL (ASM_VLO + TILE_B)    // 104448 bytes

__global__ __launch_bounds__(128, 2) void attn_kernel()
{
    extern __shared__ char smem[];
    const uint32_t uQHI = smem_u32(smem) + ASM_QHI;
    const uint32_t uQLO = smem_u32(smem) + ASM_QLO;
    const uint32_t uKHI = smem_u32(smem) + ASM_KHI;
    const uint32_t uKLO = smem_u32(smem) + ASM_KLO;
    const uint32_t uVHI = smem_u32(smem) + ASM_VHI;
    const uint32_t uVLO = smem_u32(smem) + ASM_VLO;

    const int tid  = threadIdx.x;
    const int w    = tid >> 5;
    const int lane = tid & 31;
    const int b    = blockIdx.y;
    const int qt   = NQT - 1 - ((int)blockIdx.x >> 2);   // heavy jobs first
    const int half = (int)blockIdx.x & 3;
    const int q0   = qt * 64;

    const int grp  = lane >> 2;
    const int tic  = lane & 3;
    const int rl0  = 16 * w + grp;        // local row within tile
    const int rl1  = rl0 + 8;
    const int qr0  = q0 + rl0;
    const int qr1  = q0 + rl1;

    const size_t job = ((size_t)(b * NQT + qt) * NSPLIT + half);

    // empty job: record identity partial (g_pO slot stays zero-initialized)
    if (half > qt) {
        if (tic == 0) {
            g_pm[job * 64 + rl0] = -1e30f;
            g_pl[job * 64 + rl0] = 0.f;
            g_pm[job * 64 + rl1] = -1e30f;
            g_pl[job * 64 + rl1] = 0.f;
        }
        return;
    }

    const __nv_bfloat16* kh = g_khi + (size_t)b * T_SEQ * HDIM;
    const __nv_bfloat16* kl = g_klo + (size_t)b * T_SEQ * HDIM;
    const __nv_bfloat16* vh = g_vhi + (size_t)b * T_SEQ * HDIM;
    const __nv_bfloat16* vl = g_vlo + (size_t)b * T_SEQ * HDIM;

    auto issueK = [&](int kt_) {
        const int kb = kt_ * 64;
#pragma unroll
        for (int it = 0; it < 8; it++) {
            int idx = tid + it * 128;
            int r = idx >> 4, cc = idx & 15;
            size_t go = (size_t)(kb + r) * HDIM + cc * 8;
            uint32_t so = (uint32_t)(r * LDT + cc * 8) * 2;
            cp16(uKHI + so, kh + go);
            cp16(uKLO + so, kl + go);
        }
        cp_commit();
    };
    auto issueV = [&](int kt_) {
        const int kb = kt_ * 64;
#pragma unroll
        for (int it = 0; it < 8; it++) {
            int idx = tid + it * 128;
            int r = idx >> 4, cc = idx & 15;
            size_t go = (size_t)(kb + r) * HDIM + cc * 8;
            uint32_t so = (uint32_t)(r * LDT + cc * 8) * 2;
            cp16(uVHI + so, vh + go);
            cp16(uVLO + so, vl + go);
        }
        cp_commit();
    };

    float O[16][4];
#pragma unroll
    for (int j = 0; j < 16; j++)
#pragma unroll
        for (int q = 0; q < 4; q++) O[j][q] = 0.f;
    float m0 = -1e30f, m1 = -1e30f, l0 = 0.f, l1 = 0.f;

    const int rowA  = 16 * w + (lane & 15);
    const int colA  = (lane >> 4) * 8;
    const int rowK4 = ((lane >> 4) << 3) + (lane & 7);   // x4 non-trans (j-pair)
    const int colK4 = ((lane >> 3) & 1) * 8;
    const int rowV4 = lane & 15;                         // x4 trans (jn-pair)
    const int colV4 = ((lane >> 4) & 1) * 8;

    // ---- stage Q tile hi/lo into smem (persists) + preload K,V ----
    {
        const __nv_bfloat16* qh = g_qhi + ((size_t)b * T_SEQ + q0) * HDIM;
        const __nv_bfloat16* ql = g_qlo + ((size_t)b * T_SEQ + q0) * HDIM;
#pragma unroll
        for (int it = 0; it < 8; it++) {
            int idx = tid + it * 128;
            int r = idx >> 4, cc = idx & 15;
            uint32_t so = (uint32_t)(r * LDT + cc * 8) * 2;
            cp16(uQHI + so, qh + (size_t)r * HDIM + cc * 8);
            cp16(uQLO + so, ql + (size_t)r * HDIM + cc * 8);
        }
        cp_commit();
    }
    const int kt0 = half;
    issueK(kt0);
    issueV(kt0);
    cp_wait0();
    __syncthreads();

    for (int kt = kt0; kt <= qt; kt += NSPLIT) {
        const bool has_next = (kt + NSPLIT <= qt);
        const int kb = kt * 64;

        // ---- S = Q K^T (split chain, dual accumulators, x4 B loads) ----
        float s_hh[8][4], s_x[8][4];
#pragma unroll
        for (int j = 0; j < 8; j++)
#pragma unroll
            for (int q = 0; q < 4; q++) { s_hh[j][q] = 0.f; s_x[j][q] = 0.f; }

#pragma unroll
        for (int kc = 0; kc < 8; kc++) {
            uint32_t ah[4], al[4];
            uint32_t aoff = (uint32_t)(rowA * LDT + kc * 16 + colA) * 2;
            ldmx4(ah, uQHI + aoff);
            ldmx4(al, uQLO + aoff);
#pragma unroll
            for (int jp = 0; jp < 4; jp++) {
                const int j = 2 * jp;
                uint32_t bh[4], bl[4];
                uint32_t off = (uint32_t)((8 * j + rowK4) * LDT + kc * 16 + colK4) * 2;
                ldmx4(bh, uKHI + off);
                ldmx4(bl, uKLO + off);
                mma_bf16(s_hh[j],     ah, bh[0], bh[1]);
                mma_bf16(s_x[j],      ah, bl[0], bl[1]);
                mma_bf16(s_x[j],      al, bh[0], bh[1]);
                mma_bf16(s_hh[j + 1], ah, bh[2], bh[3]);
                mma_bf16(s_x[j + 1],  ah, bl[2], bl[3]);
                mma_bf16(s_x[j + 1],  al, bh[2], bh[3]);
            }
        }
        __syncthreads();                      // done reading K bufs
        if (has_next) issueK(kt + NSPLIT);    // K prefetch flies during softmax+PV

        // ---- combine + causal mask ----
        float s[8][4];
#pragma unroll
        for (int j = 0; j < 8; j++)
#pragma unroll
            for (int q = 0; q < 4; q++) s[j][q] = s_hh[j][q] + s_x[j][q];
        if (kt == qt) {
            const int cb = kb + 2 * tic;
#pragma unroll
            for (int j = 0; j < 8; j++) {
                int c0 = cb + 8 * j, c1 = c0 + 1;
                if (c0 > qr0) s[j][0] = -1e30f;
                if (c1 > qr0) s[j][1] = -1e30f;
                if (c0 > qr1) s[j][2] = -1e30f;
                if (c1 > qr1) s[j][3] = -1e30f;
            }
        }

        // ---- online softmax (exp2 domain) ----
        float mx0 = -1e30f, mx1 = -1e30f;
#pragma unroll
        for (int j = 0; j < 8; j++) {
            mx0 = fmaxf(mx0, fmaxf(s[j][0], s[j][1]));
            mx1 = fmaxf(mx1, fmaxf(s[j][2], s[j][3]));
        }
        mx0 = fmaxf(mx0, __shfl_xor_sync(0xffffffffu, mx0, 1));
        mx0 = fmaxf(mx0, __shfl_xor_sync(0xffffffffu, mx0, 2));
        mx1 = fmaxf(mx1, __shfl_xor_sync(0xffffffffu, mx1, 1));
        mx1 = fmaxf(mx1, __shfl_xor_sync(0xffffffffu, mx1, 2));
        const float mn0 = fmaxf(m0, mx0);
        const float mn1 = fmaxf(m1, mx1);
        const float al0 = ex2(m0 - mn0);
        const float al1 = ex2(m1 - mn1);
        m0 = mn0; m1 = mn1;

        uint32_t phi[8][2], plo[8][2];
        float la0 = 0.f, la1 = 0.f;
#pragma unroll
        for (int j = 0; j < 8; j++) {
            float p0 = ex2(s[j][0] - mn0);
            float p1 = ex2(s[j][1] - mn0);
            float p2 = ex2(s[j][2] - mn1);
            float p3 = ex2(s[j][3] - mn1);
            la0 += p0 + p1; la1 += p2 + p3;
            uint32_t h0 = packbf2(p0, p1);
            uint32_t h1 = packbf2(p2, p3);
            phi[j][0] = h0; phi[j][1] = h1;
            plo[j][0] = packbf2(p0 - bflo(h0), p1 - bfhi(h0));
            plo[j][1] = packbf2(p2 - bflo(h1), p3 - bfhi(h1));
        }
        la0 += __shfl_xor_sync(0xffffffffu, la0, 1);
        la0 += __shfl_xor_sync(0xffffffffu, la0, 2);
        la1 += __shfl_xor_sync(0xffffffffu, la1, 1);
        la1 += __shfl_xor_sync(0xffffffffu, la1, 2);
        l0 = l0 * al0 + la0;
        l1 = l1 * al1 + la1;

        // skip O rescale when entire warp's alphas are exactly 1
        if (!__all_sync(0xffffffffu, (al0 == 1.f) & (al1 == 1.f))) {
#pragma unroll
            for (int j = 0; j < 16; j++) {
                O[j][0] *= al0; O[j][1] *= al0;
                O[j][2] *= al1; O[j][3] *= al1;
            }
        }

        // V(kt) must be resident: for kt>kt0 its group may still fly
        if (kt > kt0) {
            if (has_next) cp_wait1(); else cp_wait0();
            __syncthreads();
        }

        // ---- O += P V (split chain, x4 trans B loads) ----
#pragma unroll
        for (int kc = 0; kc < 4; kc++) {
            uint32_t ah[4] = { phi[2*kc][0], phi[2*kc][1], phi[2*kc+1][0], phi[2*kc+1][1] };
            uint32_t al[4] = { plo[2*kc][0], plo[2*kc][1], plo[2*kc+1][0], plo[2*kc+1][1] };
            const uint32_t offk = (uint32_t)((16 * kc + rowV4) * LDT + colV4) * 2;
#pragma unroll
            for (int jnp = 0; jnp < 8; jnp++) {
                const int jn = 2 * jnp;
                uint32_t vhf[4], vlf[4];
                uint32_t off = offk + (uint32_t)(8 * jn) * 2;
                ldmx4t(vhf, uVHI + off);
                ldmx4t(vlf, uVLO + off);
                mma_bf16(O[jn],     ah, vhf[0], vhf[1]);
                mma_bf16(O[jn],     ah, vlf[0], vlf[1]);
                mma_bf16(O[jn],     al, vhf[0], vhf[1]);
                mma_bf16(O[jn + 1], ah, vhf[2], vhf[3]);
                mma_bf16(O[jn + 1], ah, vlf[2], vlf[3]);
                mma_bf16(O[jn + 1], al, vhf[2], vhf[3]);
            }
        }
        __syncthreads();                      // done reading V bufs
        if (has_next) {
            issueV(kt + NSPLIT);              // V prefetch flies during next S
            cp_wait1();                       // K(kt+NSPLIT) resident (V still flying)
            __syncthreads();
        }
    }

    // ---- epilogue: write raw partial (O, m, l) ----
    float* pO = g_pO + job * 64 * HDIM;
    if (tic == 0) {
        g_pm[job * 64 + rl0] = m0;
        g_pl[job * 64 + rl0] = l0;
        g_pm[job * 64 + rl1] = m1;
        g_pl[job * 64 + rl1] = l1;
    }
#pragma unroll
    for (int jn = 0; jn < 16; jn++) {
        int col = 8 * jn + 2 * tic;
        *(float2*)(pO + (size_t)rl0 * HDIM + col) = make_float2(O[jn][0], O[jn][1]);
        *(float2*)(pO + (size_t)rl1 * HDIM + col) = make_float2(O[jn][2], O[jn][3]);
    }
}

// ============================================================================
// Merge: combine the NSPLIT KV-split partials per q-row (exp2 domain).
// grid (NQT, BATCH), 256 threads: row = tid>>2 (64 rows), 32 cols/thread.
// ============================================================================
__global__ __launch_bounds__(256) void merge_kernel(float* __restrict__ out)
{
    const int qt = blockIdx.x;
    const int b  = blockIdx.y;
    const int r  = threadIdx.x >> 2;         // 0..63
    const int cq = threadIdx.x & 3;          // col quarter
    const size_t j0 = ((size_t)(b * NQT + qt) * NSPLIT);

    float mM = -1e30f;
    float mv[NSPLIT], lv[NSPLIT];
#pragma unroll
    for (int i = 0; i < NSPLIT; i++) {
        mv[i] = g_pm[(j0 + i) * 64 + r];
        lv[i] = g_pl[(j0 + i) * 64 + r];
        mM = fmaxf(mM, mv[i]);
    }
    float a[NSPLIT], den = 0.f;
#pragma unroll
    for (int i = 0; i < NSPLIT; i++) {
        a[i] = ex2(mv[i] - mM);
        den += a[i] * lv[i];
    }
    const float inv = 1.f / den;

    float* orow = out + ((size_t)b * T_SEQ + qt * 64 + r) * HDIM + cq * 32;
#pragma unroll
    for (int c4 = 0; c4 < 8; c4++) {
        float4 acc = make_float4(0.f, 0.f, 0.f, 0.f);
#pragma unroll
        for (int i = 0; i < NSPLIT; i++) {
            const float* p = g_pO + (j0 + i) * 64 * HDIM + (size_t)r * HDIM + cq * 32 + c4 * 4;
            float4 v = *(const float4*)p;
            acc.x += a[i] * v.x;
            acc.y += a[i] * v.y;
            acc.z += a[i] * v.z;
            acc.w += a[i] * v.w;
        }
        acc.x *= inv; acc.y *= inv; acc.z *= inv; acc.w *= inv;
        *(float4*)(orow + c4 * 4) = acc;
    }
}

// ============================================================================
// launch
// ============================================================================
extern "C" void kernel_launch(void* const* d_in, const int* in_sizes, int n_in,
                              void* d_out, int out_size)
{
    (void)in_sizes; (void)n_in; (void)out_size;
    const float* x  = (const float*)d_in[0];
    // d_in[1] = mask (int32 causal tril) -- causality applied analytically
    const float* wq = (const float*)d_in[2];
    const float* bq = (const float*)d_in[3];
    const float* wk = (const float*)d_in[4];
    const float* bk = (const float*)d_in[5];
    const float* wv = (const float*)d_in[6];
    const float* bv = (const float*)d_in[7];
    float* out = (float*)d_out;

    split_x_kernel<<<M_ROWS * DMODEL / 4 / 256, 256>>>(x);

    dim3 gw(DMODEL / 32, HDIM / 32, 3);
    w_split_kernel<<<gw, 256>>>(wq, wk, wv);

    cudaFuncSetAttribute(qkv_hmma_kernel, cudaFuncAttributeMaxDynamicSharedMemorySize, GSM_TOTAL);
    dim3 gg(M_ROWS / 64, 3);
    qkv_hmma_kernel<<<gg, 128, GSM_TOTAL>>>(bq, bk, bv);

    cudaFuncSetAttribute(attn_kernel, cudaFuncAttributeMaxDynamicSharedMemorySize, ASM_TOTAL);
    dim3 ga(NSPLIT * NQT, BATCH);
    attn_kernel<<<ga, 128, ASM_TOTAL>>>();

    dim3 gm(NQT, BATCH);
    merge_kernel<<<gm, 256>>>(out);
}